// round 2
// baseline (speedup 1.0000x reference)
#include <cuda_runtime.h>
#include <math.h>

#define KENC 1184
#define KDEC 880

// scratch offsets (floats)
#define OFF_XCE   0u
#define OFF_XCD   151552u
#define OFF_CENC  264192u
#define OFF_CDEC  329728u
#define ZEROSPAN  395264u
#define OFF_GATES 395264u
#define OFF_MUSIG 657408u
#define OFF_HDP   683008u
#define OFF_LPRE  748544u
#define OFF_HLANG 4942848u
#define OFF_APRE  5991424u
#define OFF_WENC  8088576u
#define OFF_WDEC  10513408u
#define OFF_WMS   12315648u
#define OFF_BMS   12418048u
#define OFF_WHT   12418304u
#define OFF_MWR   12549376u
#define OFF_FYW   12672256u
#define OFF_GINV  12713216u
#define SCR_TOTAL 12713344u

__device__ float S_g[SCR_TOTAL];

__device__ __forceinline__ float sigm(float x) { return 1.f / (1.f + expf(-x)); }

// ---------- GEMM: Y[m,n] = sum_k X[m*ldx+xoff+k] * W[n*ldw+woff+k] (+b1[n]+b2[n]) ----------
template<int BM, int BN, int BK, int TM, int TN>
__global__ void gemm_k(const float* __restrict__ X, int ldx, int xoff,
                       const float* __restrict__ W, int ldw, int woff,
                       const float* __restrict__ b1, const float* __restrict__ b2,
                       float* __restrict__ Y, int ldy, int M, int N, int K)
{
    constexpr int THREADS = (BM / TM) * (BN / TN);
    constexpr int PA = (TM == 4) ? 4 : 2;
    __shared__ __align__(16) float As[BK][BM + PA];
    __shared__ __align__(16) float Bs[BK][BN + 4];
    int tid = threadIdx.x;
    int m0 = blockIdx.y * BM, n0 = blockIdx.x * BN;
    int tn = (tid % (BN / TN)) * TN;
    int tm = (tid / (BN / TN)) * TM;
    float acc[TM][TN];
#pragma unroll
    for (int i = 0; i < TM; i++)
#pragma unroll
        for (int j = 0; j < TN; j++) acc[i][j] = 0.f;

    for (int k0 = 0; k0 < K; k0 += BK) {
        for (int i = tid; i < BM * BK; i += THREADS) {
            int m = i / BK, k = i % BK;
            int gm = m0 + m, gk = k0 + k;
            As[k][m] = (gm < M && gk < K) ? X[(size_t)gm * ldx + xoff + gk] : 0.f;
        }
        for (int i = tid; i < BN * BK; i += THREADS) {
            int n = i / BK, k = i % BK;
            int gn = n0 + n, gk = k0 + k;
            Bs[k][n] = (gn < N && gk < K) ? W[(size_t)gn * ldw + woff + gk] : 0.f;
        }
        __syncthreads();
#pragma unroll
        for (int kk = 0; kk < BK; kk++) {
            float4 bv = *reinterpret_cast<const float4*>(&Bs[kk][tn]);
            float bb[4] = {bv.x, bv.y, bv.z, bv.w};
            float av[TM];
            if constexpr (TM == 4) {
                float4 a4 = *reinterpret_cast<const float4*>(&As[kk][tm]);
                av[0] = a4.x; av[1] = a4.y; av[2] = a4.z; av[3] = a4.w;
            } else {
                float2 a2 = *reinterpret_cast<const float2*>(&As[kk][tm]);
                av[0] = a2.x; av[1] = a2.y;
            }
#pragma unroll
            for (int i = 0; i < TM; i++)
#pragma unroll
                for (int j = 0; j < TN; j++) acc[i][j] += av[i] * bb[j];
        }
        __syncthreads();
    }
#pragma unroll
    for (int i = 0; i < TM; i++) {
        int gm = m0 + tm + i;
        if (gm >= M) continue;
#pragma unroll
        for (int j = 0; j < TN; j++) {
            int gn = n0 + tn + j;
            if (gn >= N) continue;
            float v = acc[i][j];
            if (b1) v += b1[gn];
            if (b2) v += b2[gn];
            Y[(size_t)gm * ldy + gn] = v;
        }
    }
}

// ---------- init: zero state + concat weights ----------
#define N_WENC (2048u*1184u)
#define N_WDEC (2048u*880u)
#define N_WMS  (200u*512u)
#define N_BMS  256u
#define N_WHT  (2u*128u*512u)
#define INIT_TOTAL (ZEROSPAN + N_WENC + N_WDEC + N_WMS + N_BMS + N_WHT)

__global__ void k_init(float* __restrict__ S,
                       const float* __restrict__ enc_Wih, const float* __restrict__ enc_Whh,
                       const float* __restrict__ dec_Wih, const float* __restrict__ dec_Whh,
                       const float* __restrict__ mu_W, const float* __restrict__ sig_W,
                       const float* __restrict__ mu_b, const float* __restrict__ sig_b,
                       const float* __restrict__ lf_Whh, const float* __restrict__ lb_Whh)
{
    for (unsigned i = blockIdx.x * blockDim.x + threadIdx.x; i < INIT_TOTAL;
         i += gridDim.x * blockDim.x) {
        unsigned r = i;
        if (r < ZEROSPAN) { S[r] = 0.f; continue; }
        r -= ZEROSPAN;
        if (r < N_WENC) {
            unsigned row = r / 1184u, col = r % 1184u;
            float v = 0.f;
            if (col < 662u) v = enc_Wih[row * 662u + col];
            else if (col < 1174u) v = enc_Whh[row * 512u + (col - 662u)];
            S[OFF_WENC + r] = v; continue;
        }
        r -= N_WENC;
        if (r < N_WDEC) {
            unsigned row = r / 880u, col = r % 880u;
            float v = 0.f;
            if (col < 356u) v = dec_Wih[row * 356u + col];
            else if (col < 868u) v = dec_Whh[row * 512u + (col - 356u)];
            S[OFF_WDEC + r] = v; continue;
        }
        r -= N_WDEC;
        if (r < N_WMS) {
            S[OFF_WMS + r] = (r < 51200u) ? mu_W[r] : sig_W[r - 51200u];
            continue;
        }
        r -= N_WMS;
        if (r < N_BMS) {
            float v = 0.f;
            if (r < 100u) v = mu_b[r];
            else if (r < 200u) v = sig_b[r - 100u];
            S[OFF_BMS + r] = v; continue;
        }
        r -= N_BMS;
        {
            unsigned dir = r / 65536u, rem = r % 65536u;
            unsigned k = rem / 512u, j = rem % 512u;
            const float* Wsrc = dir ? lb_Whh : lf_Whh;
            S[OFF_WHT + r] = Wsrc[j * 128u + k];
        }
    }
}

// ---------- bi-LSTM recurrence: 256 independent (dir,batch) chains ----------
__global__ __launch_bounds__(512) void k_bilstm(const float* __restrict__ langpre,
                                                const float* __restrict__ WhhT,
                                                float* __restrict__ hlang)
{
    int dir = blockIdx.x >> 7;
    int b = blockIdx.x & 127;
    int j = threadIdx.x;
    __shared__ float h_s[128], c_s[128], g_s[512];
    if (j < 128) { h_s[j] = 0.f; c_s[j] = 0.f; }
    __syncthreads();
    const float* pre = langpre + ((size_t)dir * 4096 + (size_t)b * 32) * 512;
    const float* Wt = WhhT + (size_t)dir * 65536;
    for (int t = 0; t < 32; t++) {
        int tt = dir ? (31 - t) : t;
        float acc = pre[(size_t)tt * 512 + j];
#pragma unroll 8
        for (int k = 0; k < 128; k++) acc += Wt[k * 512 + j] * h_s[k];
        g_s[j] = acc;
        __syncthreads();
        if (j < 128) {
            float c2 = sigm(g_s[128 + j]) * c_s[j] + sigm(g_s[j]) * tanhf(g_s[256 + j]);
            float h = sigm(g_s[384 + j]) * tanhf(c2);
            c_s[j] = c2;
            h_s[j] = h;
            hlang[((size_t)b * 32 + tt) * 256 + dir * 128 + j] = h;
        }
        __syncthreads();
    }
}

// ---------- shared filterbank (N=5) ----------
__device__ void filterbank_block(const float* p, float (*F)[5][64], float* sF, float* inv)
{
    int tid = threadIdx.x, lane = tid & 31, warp = tid >> 5;
    float gx = 32.5f * (p[0] + 1.f);
    float gy = 32.5f * (p[1] + 1.f);
    float inv2s2 = 0.5f * expf(-p[2]);
    float delta = 15.75f * expf(p[3]);
    for (int i = tid; i < 640; i += 256) {
        int f = i / 320, rem = i % 320, row = rem / 64, a = rem & 63;
        float mu = (f == 0 ? gx : gy) + ((float)row - 3.f) * delta;
        float d = (float)a - mu;
        F[f][row][a] = expf(-d * d * inv2s2);
    }
    __syncthreads();
    for (int r = warp; r < 10; r += 8) {
        int f = r / 5, row = r % 5;
        float s = F[f][row][lane] + F[f][row][lane + 32];
#pragma unroll
        for (int o = 16; o; o >>= 1) s += __shfl_xor_sync(0xffffffffu, s, o);
        if (!lane) {
            float iv = 1.f / (s + 1e-8f);
            inv[r] = iv;
            sF[r] = s * iv;
        }
    }
    __syncthreads();
    for (int i = tid; i < 640; i += 256) {
        int f = i / 320, rem = i % 320, row = rem / 64, a = rem & 63;
        F[f][row][a] *= inv[f * 5 + row];
    }
    __syncthreads();
}

// ---------- read attention + glimpse -> r into xcat_enc[:,0:150] ----------
__global__ __launch_bounds__(256) void k_read_glimpse(float* __restrict__ xcat,
                                                      const float* __restrict__ x,
                                                      const float* __restrict__ attn_W,
                                                      const float* __restrict__ attn_b)
{
    int b = blockIdx.x;
    int tid = threadIdx.x, lane = tid & 31, warp = tid >> 5;
    __shared__ float p_s[5];
    __shared__ float F_s[2][5][64];
    __shared__ float sF_s[10];
    __shared__ float inv_s[10];
    __shared__ float tmp_s[960];
    const float* hd = xcat + (size_t)b * KENC + 150;
    if (warp < 5) {
        float s = 0.f;
        for (int k = lane; k < 512; k += 32) s += hd[k] * attn_W[warp * 512 + k];
#pragma unroll
        for (int o = 16; o; o >>= 1) s += __shfl_xor_sync(0xffffffffu, s, o);
        if (!lane) p_s[warp] = s + attn_b[warp];
    }
    __syncthreads();
    float gamma = expf(p_s[4]);
    filterbank_block(p_s, F_s, sF_s, inv_s);
    // tmp[c][j][y] = sum_x img[b,c,y,x] * Fx[j][x]
    for (int i = tid; i < 960; i += 256) {
        int yy = i & 63, rest = i >> 6, j = rest % 5, c = rest / 5;
        const float* row = x + (size_t)b * 12288 + c * 4096 + yy * 64;
        float s = 0.f;
#pragma unroll 8
        for (int xx = 0; xx < 64; xx++) s += row[xx] * F_s[0][j][xx];
        tmp_s[i] = s;
    }
    __syncthreads();
    for (int o = warp; o < 75; o += 8) {
        int j = o % 5, i5 = (o / 5) % 5, c = o / 25;
        const float* tp = tmp_s + (c * 5 + j) * 64;
        float s = F_s[1][i5][lane] * tp[lane] + F_s[1][i5][lane + 32] * tp[lane + 32];
#pragma unroll
        for (int off = 16; off; off >>= 1) s += __shfl_xor_sync(0xffffffffu, s, off);
        if (!lane) {
            xcat[(size_t)b * KENC + o] = s * gamma;
            xcat[(size_t)b * KENC + 75 + o] = (s - 0.5f * sF_s[5 + i5] * sF_s[j]) * gamma;
        }
    }
}

// ---------- LSTM pointwise H=512 ----------
__global__ __launch_bounds__(512) void k_lstm_pw(const float* __restrict__ gates,
                                                 float* __restrict__ c,
                                                 float* __restrict__ o1, int ld1,
                                                 float* o2, int ld2)
{
    int b = blockIdx.x, u = threadIdx.x;
    const float* g = gates + (size_t)b * 2048;
    float cc = c[b * 512 + u];
    float c2 = sigm(g[512 + u]) * cc + sigm(g[u]) * tanhf(g[1024 + u]);
    float h = sigm(g[1536 + u]) * tanhf(c2);
    c[b * 512 + u] = c2;
    o1[(size_t)b * ld1 + u] = h;
    if (o2) o2[(size_t)b * ld2 + u] = h;
}

// ---------- alignment softmax + sent + q -> xcat_dec ----------
__global__ __launch_bounds__(256) void k_align_q(const float* __restrict__ apre,
                                                 const float* __restrict__ hdproj,
                                                 const float* __restrict__ w2,
                                                 const float* __restrict__ hlang,
                                                 const float* __restrict__ musig,
                                                 const float* __restrict__ eps_t,
                                                 float* __restrict__ xcd)
{
    int b = blockIdx.x;
    int tid = threadIdx.x, lane = tid & 31, warp = tid >> 5;
    __shared__ float hd_s[512];
    __shared__ float lg_s[32];
    for (int k = tid; k < 512; k += 256) hd_s[k] = hdproj[b * 512 + k];
    __syncthreads();
    for (int t = warp; t < 32; t += 8) {
        const float* ap = apre + ((size_t)b * 32 + t) * 512;
        float s = 0.f;
        for (int al = lane; al < 512; al += 32)
            s += tanhf(ap[al] + hd_s[al]) * w2[al];
#pragma unroll
        for (int o = 16; o; o >>= 1) s += __shfl_xor_sync(0xffffffffu, s, o);
        if (!lane) lg_s[t] = s;
    }
    __syncthreads();
    if (warp == 0) {
        float v = lg_s[lane];
        float m = v;
#pragma unroll
        for (int o = 16; o; o >>= 1) m = fmaxf(m, __shfl_xor_sync(0xffffffffu, m, o));
        float e = expf(v - m);
        float s = e;
#pragma unroll
        for (int o = 16; o; o >>= 1) s += __shfl_xor_sync(0xffffffffu, s, o);
        lg_s[lane] = e / s;
    }
    __syncthreads();
    // sent
    {
        int j = tid;
        float s = 0.f;
        const float* hl = hlang + (size_t)b * 32 * 256 + j;
#pragma unroll 8
        for (int t = 0; t < 32; t++) s += lg_s[t] * hl[t * 256];
        xcd[(size_t)b * KDEC + 100 + j] = s;
    }
    if (tid < 100) {
        float mu = musig[b * 200 + tid];
        float sp = musig[b * 200 + 100 + tid];
        xcd[(size_t)b * KDEC + tid] = mu + eps_t[b * 100 + tid] * expf(sp);
    }
}

// ---------- write prep: w=h_dec2@write_W.T+b, filterbank, M[c][i][x]=sum_j w*Fx ----------
__global__ __launch_bounds__(256) void k_write_prep(const float* __restrict__ xce,
                                                    const float* __restrict__ write_W,
                                                    const float* __restrict__ write_b,
                                                    const float* __restrict__ attn_W,
                                                    const float* __restrict__ attn_b,
                                                    float* __restrict__ Mwr,
                                                    float* __restrict__ Fyw,
                                                    float* __restrict__ ginv)
{
    int b = blockIdx.x;
    int tid = threadIdx.x, lane = tid & 31, warp = tid >> 5;
    __shared__ float hd_s[512];
    __shared__ float w_s[75];
    __shared__ float p_s[5];
    __shared__ float F_s[2][5][64];
    __shared__ float sF_s[10];
    __shared__ float inv_s[10];
    const float* hd = xce + (size_t)b * KENC + 150;
    for (int k = tid; k < 512; k += 256) hd_s[k] = hd[k];
    __syncthreads();
    for (int o = warp; o < 80; o += 8) {
        const float* row = (o < 75) ? (write_W + o * 512) : (attn_W + (o - 75) * 512);
        float s = 0.f;
        for (int k = lane; k < 512; k += 32) s += row[k] * hd_s[k];
#pragma unroll
        for (int off = 16; off; off >>= 1) s += __shfl_xor_sync(0xffffffffu, s, off);
        if (!lane) {
            if (o < 75) w_s[o] = s + write_b[o];
            else p_s[o - 75] = s + attn_b[o - 75];
        }
    }
    __syncthreads();
    if (tid == 0) ginv[b] = expf(-p_s[4]);
    filterbank_block(p_s, F_s, sF_s, inv_s);
    for (int idx = tid; idx < 960; idx += 256) {
        int xx = idx & 63, rest = idx >> 6;
        int i5 = rest % 5, c = rest / 5;
        float s = 0.f;
#pragma unroll
        for (int j = 0; j < 5; j++) s += w_s[c * 25 + i5 * 5 + j] * F_s[0][j][xx];
        Mwr[(size_t)b * 960 + rest * 64 + xx] = s;
    }
    for (int i = tid; i < 320; i += 256)
        Fyw[(size_t)b * 320 + i] = F_s[1][i >> 6][i & 63];
}

// ---------- write out: out[b,c,y,x] = ginv * sum_i Fyw[i][y]*M[c][i][x] ----------
__global__ __launch_bounds__(256) void k_write_out(const float* __restrict__ Mwr,
                                                   const float* __restrict__ Fyw,
                                                   const float* __restrict__ ginv,
                                                   float* __restrict__ out)
{
    int chunk = blockIdx.x;   // 0..47
    int b = blockIdx.y;       // 0..127
    int c = chunk >> 4;
    int tid = threadIdx.x;
    __shared__ float Ms[320], Fs[320];
    for (int i = tid; i < 320; i += 256) {
        Ms[i] = Mwr[(size_t)b * 960 + c * 320 + i];
        Fs[i] = Fyw[(size_t)b * 320 + i];
    }
    __syncthreads();
    float g = ginv[b];
    int idx = chunk * 256 + tid;
    int y = (idx >> 6) & 63;
    int xx = idx & 63;
    float s = 0.f;
#pragma unroll
    for (int i = 0; i < 5; i++) s += Fs[i * 64 + y] * Ms[i * 64 + xx];
    out[(size_t)b * 12288 + idx] = g * s;
}

// ---------- host ----------
extern "C" void kernel_launch(void* const* d_in, const int* in_sizes, int n_in,
                              void* d_out, int out_size)
{
    const float* x       = (const float*)d_in[0];
    const float* y       = (const float*)d_in[1];
    const float* eps_q   = (const float*)d_in[2];
    const float* enc_Wih = (const float*)d_in[3];
    const float* enc_Whh = (const float*)d_in[4];
    const float* enc_bih = (const float*)d_in[5];
    const float* enc_bhh = (const float*)d_in[6];
    const float* dec_Wih = (const float*)d_in[7];
    const float* dec_Whh = (const float*)d_in[8];
    const float* dec_bih = (const float*)d_in[9];
    const float* dec_bhh = (const float*)d_in[10];
    const float* mu_W    = (const float*)d_in[11];
    const float* mu_b    = (const float*)d_in[12];
    const float* sig_W   = (const float*)d_in[13];
    const float* sig_b   = (const float*)d_in[14];
    const float* write_W = (const float*)d_in[15];
    const float* write_b = (const float*)d_in[16];
    const float* align_W1= (const float*)d_in[17];
    const float* align_b1= (const float*)d_in[18];
    const float* align_w2= (const float*)d_in[19];
    const float* attn_W  = (const float*)d_in[20];
    const float* attn_b  = (const float*)d_in[21];
    const float* lf_Wih  = (const float*)d_in[22];
    const float* lf_Whh  = (const float*)d_in[23];
    const float* lf_bih  = (const float*)d_in[24];
    const float* lf_bhh  = (const float*)d_in[25];
    const float* lb_Wih  = (const float*)d_in[26];
    const float* lb_Whh  = (const float*)d_in[27];
    const float* lb_bih  = (const float*)d_in[28];
    const float* lb_bhh  = (const float*)d_in[29];
    float* out = (float*)d_out;

    float* S;
    cudaGetSymbolAddress((void**)&S, S_g);

    k_init<<<2048, 256>>>(S, enc_Wih, enc_Whh, dec_Wih, dec_Whh,
                          mu_W, sig_W, mu_b, sig_b, lf_Whh, lb_Whh);

    // language pre-activations: [dir][b*32][512]
    gemm_k<64,64,16,4,4><<<dim3(8,64), 256>>>(y, 300, 0, lf_Wih, 300, 0,
        lf_bih, lf_bhh, S + OFF_LPRE, 512, 4096, 512, 300);
    gemm_k<64,64,16,4,4><<<dim3(8,64), 256>>>(y, 300, 0, lb_Wih, 300, 0,
        lb_bih, lb_bhh, S + OFF_LPRE + 2097152u, 512, 4096, 512, 300);

    k_bilstm<<<256, 512>>>(S + OFF_LPRE, S + OFF_WHT, S + OFF_HLANG);

    // apre = hlang @ align_W1[:,512:].T + align_b1
    gemm_k<64,64,16,4,4><<<dim3(8,64), 256>>>(S + OFF_HLANG, 256, 0,
        align_W1, 768, 512, align_b1, nullptr, S + OFF_APRE, 512, 4096, 512, 256);

    for (int t = 0; t < 32; t++) {
        k_read_glimpse<<<128, 256>>>(S + OFF_XCE, x, attn_W, attn_b);

        gemm_k<32,64,32,2,4><<<dim3(32,4), 256>>>(S + OFF_XCE, KENC, 0,
            S + OFF_WENC, KENC, 0, enc_bih, enc_bhh,
            S + OFF_GATES, 2048, 128, 2048, KENC);

        k_lstm_pw<<<128, 512>>>(S + OFF_GATES, S + OFF_CENC,
                                S + OFF_XCE + 662, KENC, nullptr, 0);

        gemm_k<32,64,32,2,4><<<dim3(4,4), 256>>>(S + OFF_XCE, KENC, 662,
            S + OFF_WMS, 512, 0, S + OFF_BMS, nullptr,
            S + OFF_MUSIG, 200, 128, 200, 512);

        gemm_k<32,64,32,2,4><<<dim3(8,4), 256>>>(S + OFF_XCE, KENC, 150,
            align_W1, 768, 0, nullptr, nullptr,
            S + OFF_HDP, 512, 128, 512, 512);

        k_align_q<<<128, 256>>>(S + OFF_APRE, S + OFF_HDP, align_w2,
                                S + OFF_HLANG, S + OFF_MUSIG,
                                eps_q + (size_t)t * 12800, S + OFF_XCD);

        gemm_k<32,64,32,2,4><<<dim3(32,4), 256>>>(S + OFF_XCD, KDEC, 0,
            S + OFF_WDEC, KDEC, 0, dec_bih, dec_bhh,
            S + OFF_GATES, 2048, 128, 2048, KDEC);

        k_lstm_pw<<<128, 512>>>(S + OFF_GATES, S + OFF_CDEC,
                                S + OFF_XCE + 150, KENC,
                                S + OFF_XCD + 356, KDEC);

        k_write_prep<<<128, 256>>>(S + OFF_XCE, write_W, write_b,
                                   attn_W, attn_b,
                                   S + OFF_MWR, S + OFF_FYW, S + OFF_GINV);

        k_write_out<<<dim3(48,128), 256>>>(S + OFF_MWR, S + OFF_FYW,
                                           S + OFF_GINV,
                                           out + (size_t)t * 1572864u);
    }
}

// round 5
// speedup vs baseline: 1.3766x; 1.3766x over previous
#include <cuda_runtime.h>
#include <math.h>

#define KENC 1184
#define KDEC 880
#define NENC 2560   // 2048 gates + 512 hdproj rows

// ---- scratch offsets (floats) ----
#define OFF_XCE   0u
#define OFF_XCD   151552u
#define OFF_CENC  264192u
#define OFF_CDEC  329728u
#define ZEROSPAN  395264u
#define OFF_GATES 395264u      // 128*2560
#define OFF_LPRE  722944u      // 2*4096*512
#define OFF_HLANG 4917248u     // 128*32*256
#define OFF_APRE  5965824u     // 128*32*512
#define OFF_WENC2 8062976u     // 2560*1184
#define OFF_WDEC  11094016u    // 2048*880
#define OFF_BENC  12896256u    // 2560
#define OFF_BDEC  12898816u    // 2048
#define OFF_WHT   12900864u    // 2*128*512
#define OFF_MWR   13031936u    // 128*960
#define OFF_FYW   13154816u    // 128*320
#define OFF_GINV  13195776u    // 128
#define SCR_TOTAL 13195904u

__device__ float S_g[SCR_TOTAL];

__device__ __forceinline__ float sigm(float x) { return 1.f / (1.f + expf(-x)); }

// ---------- GEMM: Y[m,n] = sum_k X[m*ldx+xoff+k]*W[n*ldw+woff+k] (+b1[n](+b2[n])) ----------
// BM=32,BN=64,BK=32, TM=4 (row stride 8), TN=4 (col stride 16), 128 threads.
// Conflict-free: As[BK][BM+1], Bs[BK][BN+1]; strided register tiling.
__global__ __launch_bounds__(128) void gemm_k(const float* __restrict__ X, int ldx, int xoff,
                                              const float* __restrict__ W, int ldw, int woff,
                                              const float* __restrict__ b1, const float* __restrict__ b2,
                                              float* __restrict__ Y, int ldy, int M, int N, int K)
{
    __shared__ float As[32][33];
    __shared__ float Bs[32][65];
    int tid = threadIdx.x;
    int m0 = blockIdx.y * 32, n0 = blockIdx.x * 64;
    int tnb = tid & 15;        // col base (stride 16)
    int tmb = tid >> 4;        // row base (stride 8)
    float acc[4][4];
#pragma unroll
    for (int i = 0; i < 4; i++)
#pragma unroll
        for (int j = 0; j < 4; j++) acc[i][j] = 0.f;

    for (int k0 = 0; k0 < K; k0 += 32) {
#pragma unroll
        for (int it = 0; it < 8; it++) {
            int idx = tid + it * 128;
            int m = idx >> 5, k = idx & 31;
            int gm = m0 + m, gk = k0 + k;
            As[k][m] = (gm < M && gk < K) ? X[(size_t)gm * ldx + xoff + gk] : 0.f;
        }
#pragma unroll
        for (int it = 0; it < 16; it++) {
            int idx = tid + it * 128;
            int n = idx >> 5, k = idx & 31;
            int gn = n0 + n, gk = k0 + k;
            Bs[k][n] = (gn < N && gk < K) ? W[(size_t)gn * ldw + woff + gk] : 0.f;
        }
        __syncthreads();
#pragma unroll
        for (int kk = 0; kk < 32; kk++) {
            float av[4], bv[4];
#pragma unroll
            for (int i = 0; i < 4; i++) av[i] = As[kk][tmb + 8 * i];
#pragma unroll
            for (int j = 0; j < 4; j++) bv[j] = Bs[kk][tnb + 16 * j];
#pragma unroll
            for (int i = 0; i < 4; i++)
#pragma unroll
                for (int j = 0; j < 4; j++) acc[i][j] += av[i] * bv[j];
        }
        __syncthreads();
    }
#pragma unroll
    for (int i = 0; i < 4; i++) {
        int gm = m0 + tmb + 8 * i;
        if (gm >= M) continue;
#pragma unroll
        for (int j = 0; j < 4; j++) {
            int gn = n0 + tnb + 16 * j;
            if (gn >= N) continue;
            float v = acc[i][j];
            if (b1) v += b1[gn];
            if (b2) v += b2[gn];
            Y[(size_t)gm * ldy + gn] = v;
        }
    }
}

// ---------- init: zero state + concat weights/biases ----------
#define N_WENC2 (2560u*1184u)
#define N_WDEC  (2048u*880u)
#define N_WHT   (2u*128u*512u)
#define INIT_TOTAL (ZEROSPAN + N_WENC2 + N_WDEC + 2560u + 2048u + N_WHT)

__global__ void k_init(float* __restrict__ S,
                       const float* __restrict__ enc_Wih, const float* __restrict__ enc_Whh,
                       const float* __restrict__ enc_bih, const float* __restrict__ enc_bhh,
                       const float* __restrict__ dec_Wih, const float* __restrict__ dec_Whh,
                       const float* __restrict__ dec_bih, const float* __restrict__ dec_bhh,
                       const float* __restrict__ align_W1,
                       const float* __restrict__ lf_Whh, const float* __restrict__ lb_Whh)
{
    for (unsigned i = blockIdx.x * blockDim.x + threadIdx.x; i < INIT_TOTAL;
         i += gridDim.x * blockDim.x) {
        unsigned r = i;
        if (r < ZEROSPAN) { S[r] = 0.f; continue; }
        r -= ZEROSPAN;
        if (r < N_WENC2) {
            unsigned row = r / 1184u, col = r % 1184u;
            float v = 0.f;
            if (row < 2048u) {
                if (col < 662u) v = enc_Wih[row * 662u + col];
                else if (col < 1174u) v = enc_Whh[row * 512u + (col - 662u)];
            } else {
                if (col >= 150u && col < 662u)
                    v = align_W1[(row - 2048u) * 768u + (col - 150u)];
            }
            S[OFF_WENC2 + r] = v; continue;
        }
        r -= N_WENC2;
        if (r < N_WDEC) {
            unsigned row = r / 880u, col = r % 880u;
            float v = 0.f;
            if (col < 356u) v = dec_Wih[row * 356u + col];
            else if (col < 868u) v = dec_Whh[row * 512u + (col - 356u)];
            S[OFF_WDEC + r] = v; continue;
        }
        r -= N_WDEC;
        if (r < 2560u) {
            S[OFF_BENC + r] = (r < 2048u) ? (enc_bih[r] + enc_bhh[r]) : 0.f;
            continue;
        }
        r -= 2560u;
        if (r < 2048u) {
            S[OFF_BDEC + r] = dec_bih[r] + dec_bhh[r];
            continue;
        }
        r -= 2048u;
        {
            unsigned dir = r / 65536u, rem = r % 65536u;
            unsigned k = rem / 512u, j = rem % 512u;
            const float* Wsrc = dir ? lb_Whh : lf_Whh;
            S[OFF_WHT + r] = Wsrc[j * 128u + k];
        }
    }
}

// ---------- bi-LSTM recurrence ----------
__global__ __launch_bounds__(512) void k_bilstm(const float* __restrict__ langpre,
                                                const float* __restrict__ WhhT,
                                                float* __restrict__ hlang)
{
    int dir = blockIdx.x >> 7;
    int b = blockIdx.x & 127;
    int j = threadIdx.x;
    __shared__ float h_s[128], c_s[128], g_s[512];
    if (j < 128) { h_s[j] = 0.f; c_s[j] = 0.f; }
    __syncthreads();
    const float* pre = langpre + ((size_t)dir * 4096 + (size_t)b * 32) * 512;
    const float* Wt = WhhT + (size_t)dir * 65536;
    for (int t = 0; t < 32; t++) {
        int tt = dir ? (31 - t) : t;
        float acc = pre[(size_t)tt * 512 + j];
#pragma unroll 8
        for (int k = 0; k < 128; k++) acc += Wt[k * 512 + j] * h_s[k];
        g_s[j] = acc;
        __syncthreads();
        if (j < 128) {
            float c2 = sigm(g_s[128 + j]) * c_s[j] + sigm(g_s[j]) * tanhf(g_s[256 + j]);
            float h = sigm(g_s[384 + j]) * tanhf(c2);
            c_s[j] = c2;
            h_s[j] = h;
            hlang[((size_t)b * 32 + tt) * 256 + dir * 128 + j] = h;
        }
        __syncthreads();
    }
}

// ---------- shared filterbank (N=5) ----------
__device__ void filterbank_block(const float* p, float (*F)[5][64], float* sF, float* inv)
{
    int tid = threadIdx.x, lane = tid & 31, warp = tid >> 5;
    float gx = 32.5f * (p[0] + 1.f);
    float gy = 32.5f * (p[1] + 1.f);
    float inv2s2 = 0.5f * expf(-p[2]);
    float delta = 15.75f * expf(p[3]);
    for (int i = tid; i < 640; i += 256) {
        int f = i / 320, rem = i % 320, row = rem / 64, a = rem & 63;
        float mu = (f == 0 ? gx : gy) + ((float)row - 3.f) * delta;
        float d = (float)a - mu;
        F[f][row][a] = expf(-d * d * inv2s2);
    }
    __syncthreads();
    for (int r = warp; r < 10; r += 8) {
        int f = r / 5, row = r % 5;
        float s = F[f][row][lane] + F[f][row][lane + 32];
#pragma unroll
        for (int o = 16; o; o >>= 1) s += __shfl_xor_sync(0xffffffffu, s, o);
        if (!lane) {
            float iv = 1.f / (s + 1e-8f);
            inv[r] = iv;
            sF[r] = s * iv;
        }
    }
    __syncthreads();
    for (int i = tid; i < 640; i += 256) {
        int f = i / 320, rem = i % 320, row = rem / 64, a = rem & 63;
        F[f][row][a] *= inv[f * 5 + row];
    }
    __syncthreads();
}

// ---------- read attention + glimpse -> r into xcat_enc[:,0:150] ----------
__global__ __launch_bounds__(256) void k_read_glimpse(float* __restrict__ xcat,
                                                      const float* __restrict__ x,
                                                      const float* __restrict__ attn_W,
                                                      const float* __restrict__ attn_b)
{
    int b = blockIdx.x;
    int tid = threadIdx.x, lane = tid & 31, warp = tid >> 5;
    __shared__ float p_s[5];
    __shared__ float F_s[2][5][64];
    __shared__ float sF_s[10];
    __shared__ float inv_s[10];
    __shared__ float tmp_s[960];
    const float* hd = xcat + (size_t)b * KENC + 150;
    if (warp < 5) {
        float s = 0.f;
        for (int k = lane; k < 512; k += 32) s += hd[k] * attn_W[warp * 512 + k];
#pragma unroll
        for (int o = 16; o; o >>= 1) s += __shfl_xor_sync(0xffffffffu, s, o);
        if (!lane) p_s[warp] = s + attn_b[warp];
    }
    __syncthreads();
    float gamma = expf(p_s[4]);
    filterbank_block(p_s, F_s, sF_s, inv_s);
    for (int i = tid; i < 960; i += 256) {
        int yy = i & 63, rest = i >> 6, j = rest % 5, c = rest / 5;
        const float* row = x + (size_t)b * 12288 + c * 4096 + yy * 64;
        float s = 0.f;
#pragma unroll 8
        for (int xx = 0; xx < 64; xx++) s += row[xx] * F_s[0][j][xx];
        tmp_s[i] = s;
    }
    __syncthreads();
    for (int o = warp; o < 75; o += 8) {
        int j = o % 5, i5 = (o / 5) % 5, c = o / 25;
        const float* tp = tmp_s + (c * 5 + j) * 64;
        float s = F_s[1][i5][lane] * tp[lane] + F_s[1][i5][lane + 32] * tp[lane + 32];
#pragma unroll
        for (int off = 16; off; off >>= 1) s += __shfl_xor_sync(0xffffffffu, s, off);
        if (!lane) {
            xcat[(size_t)b * KENC + o] = s * gamma;
            xcat[(size_t)b * KENC + 75 + o] = (s - 0.5f * sF_s[5 + i5] * sF_s[j]) * gamma;
        }
    }
}

// ---------- fused: enc pointwise + mu/sig/q + alignment softmax + sent ----------
__global__ __launch_bounds__(256) void k_enc_fused(const float* __restrict__ gates,   // [128][2560]
                                                   float* __restrict__ cenc,
                                                   float* __restrict__ xce,
                                                   float* __restrict__ xcd,
                                                   const float* __restrict__ mu_W,
                                                   const float* __restrict__ mu_b,
                                                   const float* __restrict__ sig_W,
                                                   const float* __restrict__ sig_b,
                                                   const float* __restrict__ eps_t,   // [128][100]
                                                   const float* __restrict__ apre,    // [128][32][512]
                                                   const float* __restrict__ w2,
                                                   const float* __restrict__ hlang)   // [128][32][256]
{
    int b = blockIdx.x;
    int tid = threadIdx.x, lane = tid & 31, warp = tid >> 5;
    __shared__ float h_s[512];
    __shared__ float hd_s[512];
    __shared__ float lg_s[32];
    const float* g = gates + (size_t)b * NENC;
    // pointwise
#pragma unroll
    for (int u = tid; u < 512; u += 256) {
        float c2 = sigm(g[512 + u]) * cenc[b * 512 + u] + sigm(g[u]) * tanhf(g[1024 + u]);
        float h = sigm(g[1536 + u]) * tanhf(c2);
        cenc[b * 512 + u] = c2;
        xce[(size_t)b * KENC + 662 + u] = h;
        h_s[u] = h;
        hd_s[u] = g[2048 + u];   // hdproj
    }
    __syncthreads();
    // mu/sig -> q
    for (int o = warp; o < 100; o += 8) {
        float sm = 0.f, ss = 0.f;
        const float* mr = mu_W + o * 512;
        const float* sr = sig_W + o * 512;
        for (int k = lane; k < 512; k += 32) {
            float hv = h_s[k];
            sm += mr[k] * hv;
            ss += sr[k] * hv;
        }
#pragma unroll
        for (int off = 16; off; off >>= 1) {
            sm += __shfl_xor_sync(0xffffffffu, sm, off);
            ss += __shfl_xor_sync(0xffffffffu, ss, off);
        }
        if (!lane) {
            float mu = sm + mu_b[o];
            float sg = ss + sig_b[o];
            xcd[(size_t)b * KDEC + o] = mu + eps_t[b * 100 + o] * expf(sg);
        }
    }
    // alignment logits
    for (int t = warp; t < 32; t += 8) {
        const float* ap = apre + ((size_t)b * 32 + t) * 512;
        float s = 0.f;
        for (int al = lane; al < 512; al += 32)
            s += tanhf(ap[al] + hd_s[al]) * w2[al];
#pragma unroll
        for (int o = 16; o; o >>= 1) s += __shfl_xor_sync(0xffffffffu, s, o);
        if (!lane) lg_s[t] = s;
    }
    __syncthreads();
    if (warp == 0) {
        float v = lg_s[lane];
        float m = v;
#pragma unroll
        for (int o = 16; o; o >>= 1) m = fmaxf(m, __shfl_xor_sync(0xffffffffu, m, o));
        float e = expf(v - m);
        float s = e;
#pragma unroll
        for (int o = 16; o; o >>= 1) s += __shfl_xor_sync(0xffffffffu, s, o);
        lg_s[lane] = e / s;
    }
    __syncthreads();
    if (tid < 256) {
        int j = tid;
        float s = 0.f;
        const float* hl = hlang + (size_t)b * 8192 + j;
#pragma unroll 8
        for (int t = 0; t < 32; t++) s += lg_s[t] * hl[t * 256];
        xcd[(size_t)b * KDEC + 100 + j] = s;
    }
}

// ---------- fused: dec pointwise + write prep ----------
__global__ __launch_bounds__(256) void k_dec_fused(const float* __restrict__ gates,  // [128][2048]
                                                   float* __restrict__ cdec,
                                                   float* __restrict__ xce,
                                                   float* __restrict__ xcd,
                                                   const float* __restrict__ write_W,
                                                   const float* __restrict__ write_b,
                                                   const float* __restrict__ attn_W,
                                                   const float* __restrict__ attn_b,
                                                   float* __restrict__ Mwr,
                                                   float* __restrict__ Fyw,
                                                   float* __restrict__ ginv)
{
    int b = blockIdx.x;
    int tid = threadIdx.x, lane = tid & 31, warp = tid >> 5;
    __shared__ float h_s[512];
    __shared__ float w_s[75];
    __shared__ float p_s[5];
    __shared__ float F_s[2][5][64];
    __shared__ float sF_s[10];
    __shared__ float inv_s[10];
    const float* g = gates + (size_t)b * 2048;
#pragma unroll
    for (int u = tid; u < 512; u += 256) {
        float c2 = sigm(g[512 + u]) * cdec[b * 512 + u] + sigm(g[u]) * tanhf(g[1024 + u]);
        float h = sigm(g[1536 + u]) * tanhf(c2);
        cdec[b * 512 + u] = c2;
        xce[(size_t)b * KENC + 150 + u] = h;
        xcd[(size_t)b * KDEC + 356 + u] = h;
        h_s[u] = h;
    }
    __syncthreads();
    for (int o = warp; o < 80; o += 8) {
        const float* row = (o < 75) ? (write_W + o * 512) : (attn_W + (o - 75) * 512);
        float s = 0.f;
        for (int k = lane; k < 512; k += 32) s += row[k] * h_s[k];
#pragma unroll
        for (int off = 16; off; off >>= 1) s += __shfl_xor_sync(0xffffffffu, s, off);
        if (!lane) {
            if (o < 75) w_s[o] = s + write_b[o];
            else p_s[o - 75] = s + attn_b[o - 75];
        }
    }
    __syncthreads();
    if (tid == 0) ginv[b] = expf(-p_s[4]);
    filterbank_block(p_s, F_s, sF_s, inv_s);
    for (int idx = tid; idx < 960; idx += 256) {
        int xx = idx & 63, rest = idx >> 6;
        int i5 = rest % 5, c = rest / 5;
        float s = 0.f;
#pragma unroll
        for (int j = 0; j < 5; j++) s += w_s[c * 25 + i5 * 5 + j] * F_s[0][j][xx];
        Mwr[(size_t)b * 960 + rest * 64 + xx] = s;
    }
    for (int i = tid; i < 320; i += 256)
        Fyw[(size_t)b * 320 + i] = F_s[1][i >> 6][i & 63];
}

// ---------- write out ----------
__global__ __launch_bounds__(256) void k_write_out(const float* __restrict__ Mwr,
                                                   const float* __restrict__ Fyw,
                                                   const float* __restrict__ ginv,
                                                   float* __restrict__ out)
{
    int chunk = blockIdx.x;
    int b = blockIdx.y;
    int c = chunk >> 4;
    int tid = threadIdx.x;
    __shared__ float Ms[320], Fs[320];
    for (int i = tid; i < 320; i += 256) {
        Ms[i] = Mwr[(size_t)b * 960 + c * 320 + i];
        Fs[i] = Fyw[(size_t)b * 320 + i];
    }
    __syncthreads();
    float gv = ginv[b];
    int idx = chunk * 256 + tid;
    int y = (idx >> 6) & 63;
    int xx = idx & 63;
    float s = 0.f;
#pragma unroll
    for (int i = 0; i < 5; i++) s += Fs[i * 64 + y] * Ms[i * 64 + xx];
    out[(size_t)b * 12288 + idx] = gv * s;
}

// ---------- host ----------
extern "C" void kernel_launch(void* const* d_in, const int* in_sizes, int n_in,
                              void* d_out, int out_size)
{
    const float* x       = (const float*)d_in[0];
    const float* y       = (const float*)d_in[1];
    const float* eps_q   = (const float*)d_in[2];
    const float* enc_Wih = (const float*)d_in[3];
    const float* enc_Whh = (const float*)d_in[4];
    const float* enc_bih = (const float*)d_in[5];
    const float* enc_bhh = (const float*)d_in[6];
    const float* dec_Wih = (const float*)d_in[7];
    const float* dec_Whh = (const float*)d_in[8];
    const float* dec_bih = (const float*)d_in[9];
    const float* dec_bhh = (const float*)d_in[10];
    const float* mu_W    = (const float*)d_in[11];
    const float* mu_b    = (const float*)d_in[12];
    const float* sig_W   = (const float*)d_in[13];
    const float* sig_b   = (const float*)d_in[14];
    const float* write_W = (const float*)d_in[15];
    const float* write_b = (const float*)d_in[16];
    const float* align_W1= (const float*)d_in[17];
    const float* align_b1= (const float*)d_in[18];
    const float* align_w2= (const float*)d_in[19];
    const float* attn_W  = (const float*)d_in[20];
    const float* attn_b  = (const float*)d_in[21];
    const float* lf_Wih  = (const float*)d_in[22];
    const float* lf_Whh  = (const float*)d_in[23];
    const float* lf_bih  = (const float*)d_in[24];
    const float* lf_bhh  = (const float*)d_in[25];
    const float* lb_Wih  = (const float*)d_in[26];
    const float* lb_Whh  = (const float*)d_in[27];
    const float* lb_bih  = (const float*)d_in[28];
    const float* lb_bhh  = (const float*)d_in[29];
    float* out = (float*)d_out;

    float* S;
    cudaGetSymbolAddress((void**)&S, S_g);

    k_init<<<4096, 256>>>(S, enc_Wih, enc_Whh, enc_bih, enc_bhh,
                          dec_Wih, dec_Whh, dec_bih, dec_bhh,
                          align_W1, lf_Whh, lb_Whh);

    // language pre-activations: [dir][b*32][512]
    gemm_k<<<dim3(8, 128), 128>>>(y, 300, 0, lf_Wih, 300, 0,
        lf_bih, lf_bhh, S + OFF_LPRE, 512, 4096, 512, 300);
    gemm_k<<<dim3(8, 128), 128>>>(y, 300, 0, lb_Wih, 300, 0,
        lb_bih, lb_bhh, S + OFF_LPRE + 2097152u, 512, 4096, 512, 300);

    k_bilstm<<<256, 512>>>(S + OFF_LPRE, S + OFF_WHT, S + OFF_HLANG);

    // apre = hlang @ align_W1[:,512:].T + align_b1
    gemm_k<<<dim3(8, 128), 128>>>(S + OFF_HLANG, 256, 0,
        align_W1, 768, 512, align_b1, nullptr, S + OFF_APRE, 512, 4096, 512, 256);

    for (int t = 0; t < 32; t++) {
        k_read_glimpse<<<128, 256>>>(S + OFF_XCE, x, attn_W, attn_b);

        // enc gates + hdproj: [128, 2560] = xce[128,1184] @ WENC2[2560,1184]^T
        gemm_k<<<dim3(40, 4), 128>>>(S + OFF_XCE, KENC, 0,
            S + OFF_WENC2, KENC, 0, S + OFF_BENC, nullptr,
            S + OFF_GATES, NENC, 128, NENC, KENC);

        k_enc_fused<<<128, 256>>>(S + OFF_GATES, S + OFF_CENC,
                                  S + OFF_XCE, S + OFF_XCD,
                                  mu_W, mu_b, sig_W, sig_b,
                                  eps_q + (size_t)t * 12800,
                                  S + OFF_APRE, align_w2, S + OFF_HLANG);

        // dec gates: [128, 2048] = xcd[128,880] @ WDEC[2048,880]^T
        gemm_k<<<dim3(32, 4), 128>>>(S + OFF_XCD, KDEC, 0,
            S + OFF_WDEC, KDEC, 0, S + OFF_BDEC, nullptr,
            S + OFF_GATES, 2048, 128, 2048, KDEC);

        k_dec_fused<<<128, 256>>>(S + OFF_GATES, S + OFF_CDEC,
                                  S + OFF_XCE, S + OFF_XCD,
                                  write_W, write_b, attn_W, attn_b,
                                  S + OFF_MWR, S + OFF_FYW, S + OFF_GINV);

        k_write_out<<<dim3(48, 128), 256>>>(S + OFF_MWR, S + OFF_FYW,
                                            S + OFF_GINV,
                                            out + (size_t)t * 1572864u);
    }
}

// round 6
// speedup vs baseline: 1.7488x; 1.2704x over previous
#include <cuda_runtime.h>
#include <math.h>

#define KENC 1184
#define KDEC 880
#define NENC 2560

typedef unsigned long long ull;

// ---- scratch offsets (floats) ----
#define OFF_XCE   0u
#define OFF_XCD   151552u
#define OFF_CENC  264192u
#define OFF_CDEC  329728u
#define ZEROSPAN  395264u
#define OFF_G0    395264u       // 128*2560
#define OFF_G1    722944u       // 128*2560
#define OFF_LPRE  1050624u      // 2*4096*512
#define OFF_HLANG 5244928u      // 128*32*256
#define OFF_APRE  6293504u      // 4096*512
#define OFF_WENC2 8390656u      // 2560*1184
#define OFF_WDEC  11421440u     // 2048*880
#define OFF_BENC  13223680u     // 2560
#define OFF_BDEC  13226240u     // 2048
#define OFF_WHT   13228288u     // 2*128*512
#define OFF_BLF   13359360u     // 512
#define OFF_BLB   13359872u     // 512
#define OFF_MWR   13360384u     // 128*960
#define OFF_FYW   13483264u     // 128*320
#define OFF_GINV  13524224u     // 128
#define SCR_TOTAL 13524352u

__device__ float S_g[SCR_TOTAL];

__device__ __forceinline__ float sigm(float x) { return 1.f / (1.f + expf(-x)); }
__device__ __forceinline__ ull pk2(float lo, float hi) {
    ull r; asm("mov.b64 %0,{%1,%2};" : "=l"(r) : "f"(lo), "f"(hi)); return r;
}
__device__ __forceinline__ void upk2(ull v, float& lo, float& hi) {
    asm("mov.b64 {%0,%1},%2;" : "=f"(lo), "=f"(hi) : "l"(v));
}
__device__ __forceinline__ ull fma2(ull a, ull b, ull c) {
    ull d; asm("fma.rn.f32x2 %0,%1,%2,%3;" : "=l"(d) : "l"(a), "l"(b), "l"(c)); return d;
}

// ---------- f32x2 GEMM, BM=32 BN=64 BK=32, 256 thr, optional split-K over blockIdx.z ----------
// Y[m,n] = sum_k X[m*ldx+k]*W[n*ldw+k] (+bias[n] on z==0 output)
__global__ __launch_bounds__(256) void gemm2(const float* __restrict__ X, int ldx,
                                             const float* __restrict__ W, int ldw,
                                             const float* __restrict__ bias,
                                             float* __restrict__ Y0, float* __restrict__ Y1,
                                             int ldy, int K, int ksplit)
{
    __shared__ ull As2[32][33];
    __shared__ float Bs[32][66];
    int tid = threadIdx.x;
    int m0 = blockIdx.y * 32, n0 = blockIdx.x * 64;
    int z = blockIdx.z;
    int kstart = z ? ksplit : 0;
    int kend = z ? K : ksplit;
    float* Y = z ? Y1 : Y0;
    const float* bb = z ? nullptr : bias;
    int r = tid >> 5, c = tid & 31;
    ull acc[4] = {0ull, 0ull, 0ull, 0ull};

    for (int k0 = kstart; k0 < kend; k0 += 32) {
#pragma unroll
        for (int it = 0; it < 4; it++) {
            int idx = tid + it * 256;
            int m = idx >> 5, k = idx & 31;
            int gk = k0 + k;
            float v = (gk < kend) ? X[(size_t)(m0 + m) * ldx + gk] : 0.f;
            As2[k][m] = pk2(v, v);
        }
#pragma unroll
        for (int it = 0; it < 8; it++) {
            int idx = tid + it * 256;
            int n = idx >> 5, k = idx & 31;
            int gk = k0 + k;
            Bs[k][n] = (gk < kend) ? W[(size_t)(n0 + n) * ldw + gk] : 0.f;
        }
        __syncthreads();
#pragma unroll
        for (int kk = 0; kk < 32; kk++) {
            ull b2 = *reinterpret_cast<const ull*>(&Bs[kk][2 * c]);
#pragma unroll
            for (int i = 0; i < 4; i++)
                acc[i] = fma2(As2[kk][r + 8 * i], b2, acc[i]);
        }
        __syncthreads();
    }
#pragma unroll
    for (int i = 0; i < 4; i++) {
        int gm = m0 + r + 8 * i;
        int gn = n0 + 2 * c;
        float lo, hi;
        upk2(acc[i], lo, hi);
        if (bb) { lo += bb[gn]; hi += bb[gn + 1]; }
        *reinterpret_cast<float2*>(&Y[(size_t)gm * ldy + gn]) = make_float2(lo, hi);
    }
}

// ---------- init ----------
#define N_WENC2 (2560u*1184u)
#define N_WDEC  (2048u*880u)
#define N_WHT   (2u*128u*512u)
#define INIT_TOTAL (ZEROSPAN + N_WENC2 + N_WDEC + 2560u + 2048u + N_WHT + 1024u)

__global__ void k_init(float* __restrict__ S,
                       const float* __restrict__ enc_Wih, const float* __restrict__ enc_Whh,
                       const float* __restrict__ enc_bih, const float* __restrict__ enc_bhh,
                       const float* __restrict__ dec_Wih, const float* __restrict__ dec_Whh,
                       const float* __restrict__ dec_bih, const float* __restrict__ dec_bhh,
                       const float* __restrict__ align_W1,
                       const float* __restrict__ lf_Whh, const float* __restrict__ lb_Whh,
                       const float* __restrict__ lf_bih, const float* __restrict__ lf_bhh,
                       const float* __restrict__ lb_bih, const float* __restrict__ lb_bhh)
{
    for (unsigned i = blockIdx.x * blockDim.x + threadIdx.x; i < INIT_TOTAL;
         i += gridDim.x * blockDim.x) {
        unsigned r = i;
        if (r < ZEROSPAN) { S[r] = 0.f; continue; }
        r -= ZEROSPAN;
        if (r < N_WENC2) {
            unsigned row = r / 1184u, col = r % 1184u;
            float v = 0.f;
            if (row < 2048u) {
                if (col < 662u) v = enc_Wih[row * 662u + col];
                else if (col < 1174u) v = enc_Whh[row * 512u + (col - 662u)];
            } else {
                if (col >= 150u && col < 662u)
                    v = align_W1[(row - 2048u) * 768u + (col - 150u)];
            }
            S[OFF_WENC2 + r] = v; continue;
        }
        r -= N_WENC2;
        if (r < N_WDEC) {
            unsigned row = r / 880u, col = r % 880u;
            float v = 0.f;
            if (col < 356u) v = dec_Wih[row * 356u + col];
            else if (col < 868u) v = dec_Whh[row * 512u + (col - 356u)];
            S[OFF_WDEC + r] = v; continue;
        }
        r -= N_WDEC;
        if (r < 2560u) {
            S[OFF_BENC + r] = (r < 2048u) ? (enc_bih[r] + enc_bhh[r]) : 0.f;
            continue;
        }
        r -= 2560u;
        if (r < 2048u) { S[OFF_BDEC + r] = dec_bih[r] + dec_bhh[r]; continue; }
        r -= 2048u;
        if (r < N_WHT) {
            unsigned dir = r / 65536u, rem = r % 65536u;
            unsigned k = rem / 512u, j = rem % 512u;
            const float* Wsrc = dir ? lb_Whh : lf_Whh;
            S[OFF_WHT + r] = Wsrc[j * 128u + k];
            continue;
        }
        r -= N_WHT;
        if (r < 512u) S[OFF_BLF + r] = lf_bih[r] + lf_bhh[r];
        else S[OFF_BLB + (r - 512u)] = lb_bih[r - 512u] + lb_bhh[r - 512u];
    }
}

// ---------- bi-LSTM: 32 blocks x 512 thr, 8 batches per block, f32x2 ----------
__global__ __launch_bounds__(512) void k_bilstm8(const float* __restrict__ lpre,
                                                 const float* __restrict__ WhhT,
                                                 float* __restrict__ hlang)
{
    int dir = blockIdx.x >> 4;
    int grp = blockIdx.x & 15;
    int b0 = grp * 8;
    int tid = threadIdx.x;
    __shared__ ull h2[4][128];     // pair (b0+2p, b0+2p+1)
    __shared__ float2 c2s[4][128];
    __shared__ ull g2[4][512];
    {
        int p = tid >> 7, u = tid & 127;
        h2[p][u] = 0ull;
        c2s[p][u] = make_float2(0.f, 0.f);
    }
    __syncthreads();
    const float* Wt = WhhT + (size_t)dir * 65536;
    const float* pre = lpre + (size_t)dir * 2097152;
    int j = tid;
    for (int t = 0; t < 32; t++) {
        int tt = dir ? (31 - t) : t;
        ull acc[4];
#pragma unroll
        for (int p = 0; p < 4; p++) {
            float lo = pre[((size_t)(b0 + 2 * p) * 32 + tt) * 512 + j];
            float hi = pre[((size_t)(b0 + 2 * p + 1) * 32 + tt) * 512 + j];
            acc[p] = pk2(lo, hi);
        }
#pragma unroll 4
        for (int k = 0; k < 128; k++) {
            float w = Wt[k * 512 + j];
            ull w2 = pk2(w, w);
#pragma unroll
            for (int p = 0; p < 4; p++)
                acc[p] = fma2(w2, h2[p][k], acc[p]);
        }
#pragma unroll
        for (int p = 0; p < 4; p++) g2[p][j] = acc[p];
        __syncthreads();
        {
            int u = tid & 127, bq = tid >> 7;
            float i0, i1, f0, f1, gg0, gg1, o0, o1;
            upk2(g2[bq][u], i0, i1);
            upk2(g2[bq][128 + u], f0, f1);
            upk2(g2[bq][256 + u], gg0, gg1);
            upk2(g2[bq][384 + u], o0, o1);
            float2 cc = c2s[bq][u];
            float c20 = sigm(f0) * cc.x + sigm(i0) * tanhf(gg0);
            float c21 = sigm(f1) * cc.y + sigm(i1) * tanhf(gg1);
            float hh0 = sigm(o0) * tanhf(c20);
            float hh1 = sigm(o1) * tanhf(c21);
            c2s[bq][u] = make_float2(c20, c21);
            h2[bq][u] = pk2(hh0, hh1);
            int bA = b0 + 2 * bq, bB = bA + 1;
            hlang[((size_t)bA * 32 + tt) * 256 + dir * 128 + u] = hh0;
            hlang[((size_t)bB * 32 + tt) * 256 + dir * 128 + u] = hh1;
        }
        __syncthreads();
    }
}

// ---------- shared filterbank (N=5) ----------
__device__ void filterbank_block(const float* p, float (*F)[5][64], float* sF, float* inv)
{
    int tid = threadIdx.x, lane = tid & 31, warp = tid >> 5;
    float gx = 32.5f * (p[0] + 1.f);
    float gy = 32.5f * (p[1] + 1.f);
    float inv2s2 = 0.5f * expf(-p[2]);
    float delta = 15.75f * expf(p[3]);
    for (int i = tid; i < 640; i += 256) {
        int f = i / 320, rem = i % 320, row = rem / 64, a = rem & 63;
        float mu = (f == 0 ? gx : gy) + ((float)row - 3.f) * delta;
        float d = (float)a - mu;
        F[f][row][a] = expf(-d * d * inv2s2);
    }
    __syncthreads();
    for (int r = warp; r < 10; r += 8) {
        int f = r / 5, row = r % 5;
        float s = F[f][row][lane] + F[f][row][lane + 32];
#pragma unroll
        for (int o = 16; o; o >>= 1) s += __shfl_xor_sync(0xffffffffu, s, o);
        if (!lane) {
            float iv = 1.f / (s + 1e-8f);
            inv[r] = iv;
            sF[r] = s * iv;
        }
    }
    __syncthreads();
    for (int i = tid; i < 640; i += 256) {
        int f = i / 320, rem = i % 320, row = rem / 64, a = rem & 63;
        F[f][row][a] *= inv[f * 5 + row];
    }
    __syncthreads();
}

// ---------- glimpse from filterbank (shared code) ----------
__device__ void do_glimpse(int b, const float* __restrict__ x, float (*F)[5][64],
                           const float* sF, float gamma, float* __restrict__ xce,
                           float* tmp_s)
{
    int tid = threadIdx.x, lane = tid & 31, warp = tid >> 5;
    for (int i = tid; i < 960; i += 256) {
        int yy = i & 63, rest = i >> 6, j = rest % 5, c = rest / 5;
        const float* row = x + (size_t)b * 12288 + c * 4096 + yy * 64;
        float s = 0.f;
#pragma unroll 8
        for (int xx = 0; xx < 64; xx++) s += row[xx] * F[0][j][xx];
        tmp_s[i] = s;
    }
    __syncthreads();
    for (int o = warp; o < 75; o += 8) {
        int j = o % 5, i5 = (o / 5) % 5, c = o / 25;
        const float* tp = tmp_s + (c * 5 + j) * 64;
        float s = F[1][i5][lane] * tp[lane] + F[1][i5][lane + 32] * tp[lane + 32];
#pragma unroll
        for (int off = 16; off; off >>= 1) s += __shfl_xor_sync(0xffffffffu, s, off);
        if (!lane) {
            xce[(size_t)b * KENC + o] = s * gamma;
            xce[(size_t)b * KENC + 75 + o] = (s - 0.5f * sF[5 + i5] * sF[j]) * gamma;
        }
    }
}

// ---------- glimpse for t=0 (h_dec = 0 -> p = attn_b) ----------
__global__ __launch_bounds__(256) void k_glimpse0(float* __restrict__ xce,
                                                  const float* __restrict__ x,
                                                  const float* __restrict__ attn_b)
{
    int b = blockIdx.x;
    int tid = threadIdx.x;
    __shared__ float p_s[5];
    __shared__ float F_s[2][5][64];
    __shared__ float sF_s[10], inv_s[10];
    __shared__ float tmp_s[960];
    if (tid < 5) p_s[tid] = attn_b[tid];
    __syncthreads();
    float gamma = expf(p_s[4]);
    filterbank_block(p_s, F_s, sF_s, inv_s);
    do_glimpse(b, x, F_s, sF_s, gamma, xce, tmp_s);
}

// ---------- enc pointwise + mu/sig/q + align softmax + sent ----------
__global__ __launch_bounds__(256) void k_enc_fused(const float* __restrict__ G0,
                                                   const float* __restrict__ G1,
                                                   float* __restrict__ cenc,
                                                   float* __restrict__ xce,
                                                   float* __restrict__ xcd,
                                                   const float* __restrict__ mu_W,
                                                   const float* __restrict__ mu_b,
                                                   const float* __restrict__ sig_W,
                                                   const float* __restrict__ sig_b,
                                                   const float* __restrict__ eps_t,
                                                   const float* __restrict__ apre,
                                                   const float* __restrict__ w2,
                                                   const float* __restrict__ hlang)
{
    int b = blockIdx.x;
    int tid = threadIdx.x, lane = tid & 31, warp = tid >> 5;
    __shared__ float h_s[512];
    __shared__ float hd_s[512];
    __shared__ float lg_s[32];
    const float* g0 = G0 + (size_t)b * NENC;
    const float* g1 = G1 + (size_t)b * NENC;
#pragma unroll
    for (int u = tid; u < 512; u += 256) {
        float gi = g0[u] + g1[u];
        float gf = g0[512 + u] + g1[512 + u];
        float gg = g0[1024 + u] + g1[1024 + u];
        float go = g0[1536 + u] + g1[1536 + u];
        float c2 = sigm(gf) * cenc[b * 512 + u] + sigm(gi) * tanhf(gg);
        float h = sigm(go) * tanhf(c2);
        cenc[b * 512 + u] = c2;
        xce[(size_t)b * KENC + 662 + u] = h;
        h_s[u] = h;
        hd_s[u] = g0[2048 + u] + g1[2048 + u];
    }
    __syncthreads();
    for (int o = warp; o < 100; o += 8) {
        float sm = 0.f, ss = 0.f;
        const float* mr = mu_W + o * 512;
        const float* sr = sig_W + o * 512;
        for (int k = lane; k < 512; k += 32) {
            float hv = h_s[k];
            sm += mr[k] * hv;
            ss += sr[k] * hv;
        }
#pragma unroll
        for (int off = 16; off; off >>= 1) {
            sm += __shfl_xor_sync(0xffffffffu, sm, off);
            ss += __shfl_xor_sync(0xffffffffu, ss, off);
        }
        if (!lane) {
            float mu = sm + mu_b[o];
            float sg = ss + sig_b[o];
            xcd[(size_t)b * KDEC + o] = mu + eps_t[b * 100 + o] * expf(sg);
        }
    }
    for (int t = warp; t < 32; t += 8) {
        const float* ap = apre + ((size_t)b * 32 + t) * 512;
        float s = 0.f;
        for (int al = lane; al < 512; al += 32)
            s += tanhf(ap[al] + hd_s[al]) * w2[al];
#pragma unroll
        for (int o = 16; o; o >>= 1) s += __shfl_xor_sync(0xffffffffu, s, o);
        if (!lane) lg_s[t] = s;
    }
    __syncthreads();
    if (warp == 0) {
        float v = lg_s[lane];
        float m = v;
#pragma unroll
        for (int o = 16; o; o >>= 1) m = fmaxf(m, __shfl_xor_sync(0xffffffffu, m, o));
        float e = expf(v - m);
        float s = e;
#pragma unroll
        for (int o = 16; o; o >>= 1) s += __shfl_xor_sync(0xffffffffu, s, o);
        lg_s[lane] = e / s;
    }
    __syncthreads();
    {
        int jj = tid;
        float s = 0.f;
        const float* hl = hlang + (size_t)b * 8192 + jj;
#pragma unroll 8
        for (int t = 0; t < 32; t++) s += lg_s[t] * hl[t * 256];
        xcd[(size_t)b * KDEC + 100 + jj] = s;
    }
}

// ---------- dec pointwise + write prep + NEXT-step glimpse (same filterbank!) ----------
__global__ __launch_bounds__(256) void k_dec_fused(const float* __restrict__ G0,
                                                   const float* __restrict__ G1,
                                                   float* __restrict__ cdec,
                                                   float* __restrict__ xce,
                                                   float* __restrict__ xcd,
                                                   const float* __restrict__ x,
                                                   const float* __restrict__ write_W,
                                                   const float* __restrict__ write_b,
                                                   const float* __restrict__ attn_W,
                                                   const float* __restrict__ attn_b,
                                                   float* __restrict__ Mwr,
                                                   float* __restrict__ Fyw,
                                                   float* __restrict__ ginv,
                                                   int do_glimpse_flag)
{
    int b = blockIdx.x;
    int tid = threadIdx.x, lane = tid & 31, warp = tid >> 5;
    __shared__ float h_s[512];
    __shared__ float w_s[75];
    __shared__ float p_s[5];
    __shared__ float F_s[2][5][64];
    __shared__ float sF_s[10], inv_s[10];
    __shared__ float tmp_s[960];
    const float* g0 = G0 + (size_t)b * 2048;
    const float* g1 = G1 + (size_t)b * 2048;
#pragma unroll
    for (int u = tid; u < 512; u += 256) {
        float gi = g0[u] + g1[u];
        float gf = g0[512 + u] + g1[512 + u];
        float gg = g0[1024 + u] + g1[1024 + u];
        float go = g0[1536 + u] + g1[1536 + u];
        float c2 = sigm(gf) * cdec[b * 512 + u] + sigm(gi) * tanhf(gg);
        float h = sigm(go) * tanhf(c2);
        cdec[b * 512 + u] = c2;
        xce[(size_t)b * KENC + 150 + u] = h;
        xcd[(size_t)b * KDEC + 356 + u] = h;
        h_s[u] = h;
    }
    __syncthreads();
    for (int o = warp; o < 80; o += 8) {
        const float* row = (o < 75) ? (write_W + o * 512) : (attn_W + (o - 75) * 512);
        float s = 0.f;
        for (int k = lane; k < 512; k += 32) s += row[k] * h_s[k];
#pragma unroll
        for (int off = 16; off; off >>= 1) s += __shfl_xor_sync(0xffffffffu, s, off);
        if (!lane) {
            if (o < 75) w_s[o] = s + write_b[o];
            else p_s[o - 75] = s + attn_b[o - 75];
        }
    }
    __syncthreads();
    if (tid == 0) ginv[b] = expf(-p_s[4]);
    float gamma = expf(p_s[4]);
    filterbank_block(p_s, F_s, sF_s, inv_s);
    // write-side: M[c][i][x] = sum_j w[c,i,j] * Fx[j][x]
    for (int idx = tid; idx < 960; idx += 256) {
        int xx = idx & 63, rest = idx >> 6;
        int i5 = rest % 5, c = rest / 5;
        float s = 0.f;
#pragma unroll
        for (int jj = 0; jj < 5; jj++) s += w_s[c * 25 + i5 * 5 + jj] * F_s[0][jj][xx];
        Mwr[(size_t)b * 960 + rest * 64 + xx] = s;
    }
    for (int i = tid; i < 320; i += 256)
        Fyw[(size_t)b * 320 + i] = F_s[1][i >> 6][i & 63];
    __syncthreads();
    // read-side glimpse for next step: identical filterbank (RN==WN==5, same h_dec)
    if (do_glimpse_flag)
        do_glimpse(b, x, F_s, sF_s, gamma, xce, tmp_s);
}

// ---------- write out ----------
__global__ __launch_bounds__(256) void k_write_out(const float* __restrict__ Mwr,
                                                   const float* __restrict__ Fyw,
                                                   const float* __restrict__ ginv,
                                                   float* __restrict__ out)
{
    int chunk = blockIdx.x;
    int b = blockIdx.y;
    int c = chunk >> 4;
    int tid = threadIdx.x;
    __shared__ float Ms[320], Fs[320];
    for (int i = tid; i < 320; i += 256) {
        Ms[i] = Mwr[(size_t)b * 960 + c * 320 + i];
        Fs[i] = Fyw[(size_t)b * 320 + i];
    }
    __syncthreads();
    float gv = ginv[b];
    int idx = chunk * 256 + tid;
    int y = (idx >> 6) & 63;
    int xx = idx & 63;
    float s = 0.f;
#pragma unroll
    for (int i = 0; i < 5; i++) s += Fs[i * 64 + y] * Ms[i * 64 + xx];
    out[(size_t)b * 12288 + idx] = gv * s;
}

// ---------- host ----------
extern "C" void kernel_launch(void* const* d_in, const int* in_sizes, int n_in,
                              void* d_out, int out_size)
{
    const float* x       = (const float*)d_in[0];
    const float* y       = (const float*)d_in[1];
    const float* eps_q   = (const float*)d_in[2];
    const float* enc_Wih = (const float*)d_in[3];
    const float* enc_Whh = (const float*)d_in[4];
    const float* enc_bih = (const float*)d_in[5];
    const float* enc_bhh = (const float*)d_in[6];
    const float* dec_Wih = (const float*)d_in[7];
    const float* dec_Whh = (const float*)d_in[8];
    const float* dec_bih = (const float*)d_in[9];
    const float* dec_bhh = (const float*)d_in[10];
    const float* mu_W    = (const float*)d_in[11];
    const float* mu_b    = (const float*)d_in[12];
    const float* sig_W   = (const float*)d_in[13];
    const float* sig_b   = (const float*)d_in[14];
    const float* write_W = (const float*)d_in[15];
    const float* write_b = (const float*)d_in[16];
    const float* align_W1= (const float*)d_in[17];
    const float* align_b1= (const float*)d_in[18];
    const float* align_w2= (const float*)d_in[19];
    const float* attn_W  = (const float*)d_in[20];
    const float* attn_b  = (const float*)d_in[21];
    const float* lf_Wih  = (const float*)d_in[22];
    const float* lf_Whh  = (const float*)d_in[23];
    const float* lf_bih  = (const float*)d_in[24];
    const float* lf_bhh  = (const float*)d_in[25];
    const float* lb_Wih  = (const float*)d_in[26];
    const float* lb_Whh  = (const float*)d_in[27];
    const float* lb_bih  = (const float*)d_in[28];
    const float* lb_bhh  = (const float*)d_in[29];
    float* out = (float*)d_out;

    float* S;
    cudaGetSymbolAddress((void**)&S, S_g);

    k_init<<<4096, 256>>>(S, enc_Wih, enc_Whh, enc_bih, enc_bhh,
                          dec_Wih, dec_Whh, dec_bih, dec_bhh,
                          align_W1, lf_Whh, lb_Whh,
                          lf_bih, lf_bhh, lb_bih, lb_bhh);

    // language pre-activations (M=4096, N=512, K=300)
    gemm2<<<dim3(8, 128, 1), 256>>>(y, 300, lf_Wih, 300, S + OFF_BLF,
                                    S + OFF_LPRE, nullptr, 512, 300, 300);
    gemm2<<<dim3(8, 128, 1), 256>>>(y, 300, lb_Wih, 300, S + OFF_BLB,
                                    S + OFF_LPRE + 2097152u, nullptr, 512, 300, 300);

    k_bilstm8<<<32, 512>>>(S + OFF_LPRE, S + OFF_WHT, S + OFF_HLANG);

    // apre = hlang @ align_W1[:,512:].T + align_b1  (M=4096, N=512, K=256)
    gemm2<<<dim3(8, 128, 1), 256>>>(S + OFF_HLANG, 256, align_W1 + 512, 768,
                                    align_b1, S + OFF_APRE, nullptr, 512, 256, 256);

    k_glimpse0<<<128, 256>>>(S + OFF_XCE, x, attn_b);

    for (int t = 0; t < 32; t++) {
        // enc gates + hdproj: M=128 N=2560 K=1184, split-K (608/576)
        gemm2<<<dim3(40, 4, 2), 256>>>(S + OFF_XCE, KENC, S + OFF_WENC2, KENC,
                                       S + OFF_BENC, S + OFF_G0, S + OFF_G1,
                                       NENC, KENC, 608);

        k_enc_fused<<<128, 256>>>(S + OFF_G0, S + OFF_G1, S + OFF_CENC,
                                  S + OFF_XCE, S + OFF_XCD,
                                  mu_W, mu_b, sig_W, sig_b,
                                  eps_q + (size_t)t * 12800,
                                  S + OFF_APRE, align_w2, S + OFF_HLANG);

        // dec gates: M=128 N=2048 K=880, split-K (448/432)
        gemm2<<<dim3(32, 4, 2), 256>>>(S + OFF_XCD, KDEC, S + OFF_WDEC, KDEC,
                                       S + OFF_BDEC, S + OFF_G0, S + OFF_G1,
                                       2048, KDEC, 448);

        k_dec_fused<<<128, 256>>>(S + OFF_G0, S + OFF_G1, S + OFF_CDEC,
                                  S + OFF_XCE, S + OFF_XCD, x,
                                  write_W, write_b, attn_W, attn_b,
                                  S + OFF_MWR, S + OFF_FYW, S + OFF_GINV,
                                  (t < 31) ? 1 : 0);

        k_write_out<<<dim3(48, 128), 256>>>(S + OFF_MWR, S + OFF_FYW,
                                            S + OFF_GINV,
                                            out + (size_t)t * 1572864u);
    }
}

// round 9
// speedup vs baseline: 1.9138x; 1.0944x over previous
#include <cuda_runtime.h>
#include <math.h>

#define KENC 1184
#define KDEC 880
#define NENC 2560
#define GPART 327680u   // 128*2560 part stride

typedef unsigned long long ull;

// ---- scratch offsets (floats) ----
#define OFF_XCE   0u
#define OFF_XCD   151552u
#define OFF_CENC  264192u
#define OFF_CDEC  329728u
#define ZEROSPAN  395264u
#define OFF_G     395264u       // 4 * 327680
#define OFF_LPRE  1705984u      // 2*4096*512
#define OFF_HLANG 5900288u      // 128*32*256
#define OFF_APRE  6948864u      // 4096*512
#define OFF_WENC2 9046016u      // 2560*1184
#define OFF_WDEC  12077056u     // 2048*880
#define OFF_BENC  13879296u     // 2560
#define OFF_BDEC  13881856u     // 2048
#define OFF_WHT   13883904u     // 2*128*512
#define OFF_BLF   14014976u     // 512
#define OFF_BLB   14015488u     // 512
#define SCR_TOTAL 14016000u

__device__ float S_g[SCR_TOTAL];

__device__ __forceinline__ float sigm(float x) { return 1.f / (1.f + expf(-x)); }
__device__ __forceinline__ ull pk2(float lo, float hi) {
    ull r; asm("mov.b64 %0,{%1,%2};" : "=l"(r) : "f"(lo), "f"(hi)); return r;
}
__device__ __forceinline__ void upk2(ull v, float& lo, float& hi) {
    asm("mov.b64 {%0,%1},%2;" : "=f"(lo), "=f"(hi) : "l"(v));
}
__device__ __forceinline__ ull fma2(ull a, ull b, ull c) {
    ull d; asm("fma.rn.f32x2 %0,%1,%2,%3;" : "=l"(d) : "l"(a), "l"(b), "l"(c)); return d;
}

// ---------- f32x2 GEMM: BM=64 BN=128 BK=16, 256 thr, 8x4 per thread, split-K on z ----------
__global__ __launch_bounds__(256) void gemm2b(const float* __restrict__ X, int ldx,
                                              const float* __restrict__ W, int ldw,
                                              const float* __restrict__ bias,
                                              float* __restrict__ Y, int ldy,
                                              unsigned partStride, int K, int KS)
{
    __shared__ ull  As2[16][65];
    __shared__ float Bs[16][132];
    int tid = threadIdx.x;
    int m0 = blockIdx.y * 64, n0 = blockIdx.x * 128;
    int z = blockIdx.z;
    int kbeg = z * KS;
    int kend = min(K, kbeg + KS);
    float* Yp = Y + (size_t)z * partStride;
    const float* bb = (z == 0) ? bias : nullptr;
    int warp = tid >> 5, lane = tid & 31;
    int w8 = warp * 8;
    ull acc0[8], acc1[8];
#pragma unroll
    for (int i = 0; i < 8; i++) { acc0[i] = 0ull; acc1[i] = 0ull; }

    for (int k0 = kbeg; k0 < kend; k0 += 16) {
#pragma unroll
        for (int it = 0; it < 4; it++) {
            int idx = tid + it * 256;
            int m = idx >> 4, k = idx & 15;
            int gk = k0 + k;
            float v = (gk < kend) ? X[(size_t)(m0 + m) * ldx + gk] : 0.f;
            As2[k][m] = pk2(v, v);
        }
#pragma unroll
        for (int it = 0; it < 8; it++) {
            int idx = tid + it * 256;
            int n = idx >> 4, k = idx & 15;
            int gk = k0 + k;
            Bs[k][n] = (gk < kend) ? W[(size_t)(n0 + n) * ldw + gk] : 0.f;
        }
        __syncthreads();
#pragma unroll
        for (int kk = 0; kk < 16; kk++) {
            ull b0 = *reinterpret_cast<const ull*>(&Bs[kk][2 * lane]);
            ull b1 = *reinterpret_cast<const ull*>(&Bs[kk][2 * lane + 64]);
#pragma unroll
            for (int i = 0; i < 8; i++) {
                ull a = As2[kk][w8 + i];
                acc0[i] = fma2(a, b0, acc0[i]);
                acc1[i] = fma2(a, b1, acc1[i]);
            }
        }
        __syncthreads();
    }
#pragma unroll
    for (int i = 0; i < 8; i++) {
        int gm = m0 + w8 + i;
        int gn = n0 + 2 * lane;
        float lo, hi;
        upk2(acc0[i], lo, hi);
        if (bb) { lo += bb[gn]; hi += bb[gn + 1]; }
        *reinterpret_cast<float2*>(&Yp[(size_t)gm * ldy + gn]) = make_float2(lo, hi);
        upk2(acc1[i], lo, hi);
        if (bb) { lo += bb[gn + 64]; hi += bb[gn + 65]; }
        *reinterpret_cast<float2*>(&Yp[(size_t)gm * ldy + gn + 64]) = make_float2(lo, hi);
    }
}

// ---------- init ----------
#define N_WENC2 (2560u*1184u)
#define N_WDEC  (2048u*880u)
#define N_WHT   (2u*128u*512u)
#define INIT_TOTAL (ZEROSPAN + N_WENC2 + N_WDEC + 2560u + 2048u + N_WHT + 1024u)

__global__ void k_init(float* __restrict__ S,
                       const float* __restrict__ enc_Wih, const float* __restrict__ enc_Whh,
                       const float* __restrict__ enc_bih, const float* __restrict__ enc_bhh,
                       const float* __restrict__ dec_Wih, const float* __restrict__ dec_Whh,
                       const float* __restrict__ dec_bih, const float* __restrict__ dec_bhh,
                       const float* __restrict__ align_W1,
                       const float* __restrict__ lf_Whh, const float* __restrict__ lb_Whh,
                       const float* __restrict__ lf_bih, const float* __restrict__ lf_bhh,
                       const float* __restrict__ lb_bih, const float* __restrict__ lb_bhh)
{
    for (unsigned i = blockIdx.x * blockDim.x + threadIdx.x; i < INIT_TOTAL;
         i += gridDim.x * blockDim.x) {
        unsigned r = i;
        if (r < ZEROSPAN) { S[r] = 0.f; continue; }
        r -= ZEROSPAN;
        if (r < N_WENC2) {
            unsigned row = r / 1184u, col = r % 1184u;
            float v = 0.f;
            if (row < 2048u) {
                if (col < 662u) v = enc_Wih[row * 662u + col];
                else if (col < 1174u) v = enc_Whh[row * 512u + (col - 662u)];
            } else {
                if (col >= 150u && col < 662u)
                    v = align_W1[(row - 2048u) * 768u + (col - 150u)];
            }
            S[OFF_WENC2 + r] = v; continue;
        }
        r -= N_WENC2;
        if (r < N_WDEC) {
            unsigned row = r / 880u, col = r % 880u;
            float v = 0.f;
            if (col < 356u) v = dec_Wih[row * 356u + col];
            else if (col < 868u) v = dec_Whh[row * 512u + (col - 356u)];
            S[OFF_WDEC + r] = v; continue;
        }
        r -= N_WDEC;
        if (r < 2560u) {
            S[OFF_BENC + r] = (r < 2048u) ? (enc_bih[r] + enc_bhh[r]) : 0.f;
            continue;
        }
        r -= 2560u;
        if (r < 2048u) { S[OFF_BDEC + r] = dec_bih[r] + dec_bhh[r]; continue; }
        r -= 2048u;
        if (r < N_WHT) {
            unsigned dir = r / 65536u, rem = r % 65536u;
            unsigned k = rem / 512u, j = rem % 512u;
            const float* Wsrc = dir ? lb_Whh : lf_Whh;
            S[OFF_WHT + r] = Wsrc[j * 128u + k];
            continue;
        }
        r -= N_WHT;
        if (r < 512u) S[OFF_BLF + r] = lf_bih[r] + lf_bhh[r];
        else S[OFF_BLB + (r - 512u)] = lb_bih[r - 512u] + lb_bhh[r - 512u];
    }
}

// ---------- bi-LSTM: 128 blocks x 512 thr, one f32x2 batch-pair per block ----------
__global__ __launch_bounds__(512) void k_bilstm_pair(const float* __restrict__ lpre,
                                                     const float* __restrict__ WhhT,
                                                     float* __restrict__ hlang)
{
    int dir = blockIdx.x >> 6;
    int pr = blockIdx.x & 63;
    int b0 = pr * 2;
    int tid = threadIdx.x;
    __shared__ ull h2[128];
    __shared__ float2 c2s[128];
    __shared__ ull g2[512];
    if (tid < 128) { h2[tid] = 0ull; c2s[tid] = make_float2(0.f, 0.f); }
    __syncthreads();
    const float* Wt = WhhT + (size_t)dir * 65536;
    const float* pre = lpre + (size_t)dir * 2097152;
    int j = tid;
    for (int t = 0; t < 32; t++) {
        int tt = dir ? (31 - t) : t;
        float lo = pre[((size_t)b0 * 32 + tt) * 512 + j];
        float hi = pre[((size_t)(b0 + 1) * 32 + tt) * 512 + j];
        ull acc = pk2(lo, hi);
#pragma unroll 8
        for (int k = 0; k < 128; k++) {
            float w = Wt[k * 512 + j];
            acc = fma2(pk2(w, w), h2[k], acc);
        }
        g2[j] = acc;
        __syncthreads();
        if (tid < 128) {
            int u = tid;
            float i0, i1, f0, f1, gg0, gg1, o0, o1;
            upk2(g2[u], i0, i1);
            upk2(g2[128 + u], f0, f1);
            upk2(g2[256 + u], gg0, gg1);
            upk2(g2[384 + u], o0, o1);
            float2 cc = c2s[u];
            float c20 = sigm(f0) * cc.x + sigm(i0) * tanhf(gg0);
            float c21 = sigm(f1) * cc.y + sigm(i1) * tanhf(gg1);
            float hh0 = sigm(o0) * tanhf(c20);
            float hh1 = sigm(o1) * tanhf(c21);
            c2s[u] = make_float2(c20, c21);
            h2[u] = pk2(hh0, hh1);
            hlang[((size_t)b0 * 32 + tt) * 256 + dir * 128 + u] = hh0;
            hlang[((size_t)(b0 + 1) * 32 + tt) * 256 + dir * 128 + u] = hh1;
        }
        __syncthreads();
    }
}

// ---------- shared filterbank (N=5) ----------
__device__ void filterbank_block(const float* p, float (*F)[5][64], float* sF, float* inv)
{
    int tid = threadIdx.x, lane = tid & 31, warp = tid >> 5;
    float gx = 32.5f * (p[0] + 1.f);
    float gy = 32.5f * (p[1] + 1.f);
    float inv2s2 = 0.5f * expf(-p[2]);
    float delta = 15.75f * expf(p[3]);
    for (int i = tid; i < 640; i += 256) {
        int f = i / 320, rem = i % 320, row = rem / 64, a = rem & 63;
        float mu = (f == 0 ? gx : gy) + ((float)row - 3.f) * delta;
        float d = (float)a - mu;
        F[f][row][a] = expf(-d * d * inv2s2);
    }
    __syncthreads();
    for (int r = warp; r < 10; r += 8) {
        int f = r / 5, row = r % 5;
        float s = F[f][row][lane] + F[f][row][lane + 32];
#pragma unroll
        for (int o = 16; o; o >>= 1) s += __shfl_xor_sync(0xffffffffu, s, o);
        if (!lane) {
            float iv = 1.f / (s + 1e-8f);
            inv[r] = iv;
            sF[r] = s * iv;
        }
    }
    __syncthreads();
    for (int i = tid; i < 640; i += 256) {
        int f = i / 320, rem = i % 320, row = rem / 64, a = rem & 63;
        F[f][row][a] *= inv[f * 5 + row];
    }
    __syncthreads();
}

// ---------- glimpse from filterbank ----------
__device__ void do_glimpse(int b, const float* __restrict__ x, float (*F)[5][64],
                           const float* sF, float gamma, float* __restrict__ xce,
                           float* tmp_s)
{
    int tid = threadIdx.x, lane = tid & 31, warp = tid >> 5;
    for (int i = tid; i < 960; i += 256) {
        int yy = i & 63, rest = i >> 6, j = rest % 5, c = rest / 5;
        const float* row = x + (size_t)b * 12288 + c * 4096 + yy * 64;
        float s = 0.f;
#pragma unroll 8
        for (int xx = 0; xx < 64; xx++) s += row[xx] * F[0][j][xx];
        tmp_s[i] = s;
    }
    __syncthreads();
    for (int o = warp; o < 75; o += 8) {
        int j = o % 5, i5 = (o / 5) % 5, c = o / 25;
        const float* tp = tmp_s + (c * 5 + j) * 64;
        float s = F[1][i5][lane] * tp[lane] + F[1][i5][lane + 32] * tp[lane + 32];
#pragma unroll
        for (int off = 16; off; off >>= 1) s += __shfl_xor_sync(0xffffffffu, s, off);
        if (!lane) {
            xce[(size_t)b * KENC + o] = s * gamma;
            xce[(size_t)b * KENC + 75 + o] = (s - 0.5f * sF[5 + i5] * sF[j]) * gamma;
        }
    }
}

// ---------- glimpse t=0 (h_dec=0 -> p=attn_b) ----------
__global__ __launch_bounds__(256) void k_glimpse0(float* __restrict__ xce,
                                                  const float* __restrict__ x,
                                                  const float* __restrict__ attn_b)
{
    int b = blockIdx.x;
    int tid = threadIdx.x;
    __shared__ float p_s[5];
    __shared__ float F_s[2][5][64];
    __shared__ float sF_s[10], inv_s[10];
    __shared__ float tmp_s[960];
    if (tid < 5) p_s[tid] = attn_b[tid];
    __syncthreads();
    float gamma = expf(p_s[4]);
    filterbank_block(p_s, F_s, sF_s, inv_s);
    do_glimpse(b, x, F_s, sF_s, gamma, xce, tmp_s);
}

// ---------- enc pointwise (sum 4 parts) + mu/sig/q + align softmax + sent ----------
__global__ __launch_bounds__(256) void k_enc_fused(const float* __restrict__ G,
                                                   float* __restrict__ cenc,
                                                   float* __restrict__ xce,
                                                   float* __restrict__ xcd,
                                                   const float* __restrict__ benc,
                                                   const float* __restrict__ mu_W,
                                                   const float* __restrict__ mu_b,
                                                   const float* __restrict__ sig_W,
                                                   const float* __restrict__ sig_b,
                                                   const float* __restrict__ eps_t,
                                                   const float* __restrict__ apre,
                                                   const float* __restrict__ w2,
                                                   const float* __restrict__ hlang)
{
    int b = blockIdx.x;
    int tid = threadIdx.x, lane = tid & 31, warp = tid >> 5;
    __shared__ float h_s[512];
    __shared__ float hd_s[512];
    __shared__ float lg_s[32];
    const float* g0 = G + (size_t)b * NENC;
#pragma unroll
    for (int u = tid; u < 512; u += 256) {
        float gi = benc[u], gf = benc[512 + u], gg = benc[1024 + u], go = benc[1536 + u];
        float hp = 0.f;
#pragma unroll
        for (int z = 0; z < 4; z++) {
            const float* gz = g0 + (size_t)z * GPART;
            gi += gz[u]; gf += gz[512 + u]; gg += gz[1024 + u]; go += gz[1536 + u];
            hp += gz[2048 + u];
        }
        float c2 = sigm(gf) * cenc[b * 512 + u] + sigm(gi) * tanhf(gg);
        float h = sigm(go) * tanhf(c2);
        cenc[b * 512 + u] = c2;
        xce[(size_t)b * KENC + 662 + u] = h;
        h_s[u] = h;
        hd_s[u] = hp;
    }
    __syncthreads();
    for (int o = warp; o < 100; o += 8) {
        float sm = 0.f, ss = 0.f;
        const float* mr = mu_W + o * 512;
        const float* sr = sig_W + o * 512;
        for (int k = lane; k < 512; k += 32) {
            float hv = h_s[k];
            sm += mr[k] * hv;
            ss += sr[k] * hv;
        }
#pragma unroll
        for (int off = 16; off; off >>= 1) {
            sm += __shfl_xor_sync(0xffffffffu, sm, off);
            ss += __shfl_xor_sync(0xffffffffu, ss, off);
        }
        if (!lane) {
            float mu = sm + mu_b[o];
            float sg = ss + sig_b[o];
            xcd[(size_t)b * KDEC + o] = mu + eps_t[b * 100 + o] * expf(sg);
        }
    }
    for (int t = warp; t < 32; t += 8) {
        const float* ap = apre + ((size_t)b * 32 + t) * 512;
        float s = 0.f;
        for (int al = lane; al < 512; al += 32)
            s += tanhf(ap[al] + hd_s[al]) * w2[al];
#pragma unroll
        for (int o = 16; o; o >>= 1) s += __shfl_xor_sync(0xffffffffu, s, o);
        if (!lane) lg_s[t] = s;
    }
    __syncthreads();
    if (warp == 0) {
        float v = lg_s[lane];
        float m = v;
#pragma unroll
        for (int o = 16; o; o >>= 1) m = fmaxf(m, __shfl_xor_sync(0xffffffffu, m, o));
        float e = expf(v - m);
        float s = e;
#pragma unroll
        for (int o = 16; o; o >>= 1) s += __shfl_xor_sync(0xffffffffu, s, o);
        lg_s[lane] = e / s;
    }
    __syncthreads();
    {
        int jj = tid;
        float s = 0.f;
        const float* hl = hlang + (size_t)b * 8192 + jj;
#pragma unroll 8
        for (int t = 0; t < 32; t++) s += lg_s[t] * hl[t * 256];
        xcd[(size_t)b * KDEC + 100 + jj] = s;
    }
}

// ---------- dec pointwise (4 parts) + write window + OUTPUT + next-step glimpse ----------
__global__ __launch_bounds__(256) void k_dec_fused(const float* __restrict__ G,
                                                   float* __restrict__ cdec,
                                                   float* __restrict__ xce,
                                                   float* __restrict__ xcd,
                                                   const float* __restrict__ x,
                                                   const float* __restrict__ bdec,
                                                   const float* __restrict__ write_W,
                                                   const float* __restrict__ write_b,
                                                   const float* __restrict__ attn_W,
                                                   const float* __restrict__ attn_b,
                                                   float* __restrict__ out,
                                                   int do_glimpse_flag)
{
    int b = blockIdx.x;
    int tid = threadIdx.x, lane = tid & 31, warp = tid >> 5;
    __shared__ float h_s[512];
    __shared__ float w_s[75];
    __shared__ float p_s[5];
    __shared__ float F_s[2][5][64];
    __shared__ float sF_s[10], inv_s[10];
    __shared__ float Mw_s[960];
    __shared__ float tmp_s[960];
    const float* g0 = G + (size_t)b * 2048;
#pragma unroll
    for (int u = tid; u < 512; u += 256) {
        float gi = bdec[u], gf = bdec[512 + u], gg = bdec[1024 + u], go = bdec[1536 + u];
#pragma unroll
        for (int z = 0; z < 4; z++) {
            const float* gz = g0 + (size_t)z * GPART;
            gi += gz[u]; gf += gz[512 + u]; gg += gz[1024 + u]; go += gz[1536 + u];
        }
        float c2 = sigm(gf) * cdec[b * 512 + u] + sigm(gi) * tanhf(gg);
        float h = sigm(go) * tanhf(c2);
        cdec[b * 512 + u] = c2;
        xce[(size_t)b * KENC + 150 + u] = h;
        xcd[(size_t)b * KDEC + 356 + u] = h;
        h_s[u] = h;
    }
    __syncthreads();
    for (int o = warp; o < 80; o += 8) {
        const float* row = (o < 75) ? (write_W + o * 512) : (attn_W + (o - 75) * 512);
        float s = 0.f;
        for (int k = lane; k < 512; k += 32) s += row[k] * h_s[k];
#pragma unroll
        for (int off = 16; off; off >>= 1) s += __shfl_xor_sync(0xffffffffu, s, off);
        if (!lane) {
            if (o < 75) w_s[o] = s + write_b[o];
            else p_s[o - 75] = s + attn_b[o - 75];
        }
    }
    __syncthreads();
    float gamma = expf(p_s[4]);
    float ginv = expf(-p_s[4]);
    filterbank_block(p_s, F_s, sF_s, inv_s);
    for (int idx = tid; idx < 960; idx += 256) {
        int xx = idx & 63, rest = idx >> 6;
        int i5 = rest % 5, c = rest / 5;
        float s = 0.f;
#pragma unroll
        for (int jj = 0; jj < 5; jj++) s += w_s[c * 25 + i5 * 5 + jj] * F_s[0][jj][xx];
        Mw_s[idx] = s;
    }
    __syncthreads();
    for (int idx = tid; idx < 12288; idx += 256) {
        int xx = idx & 63, yy = (idx >> 6) & 63, c = idx >> 12;
        float s = 0.f;
#pragma unroll
        for (int i = 0; i < 5; i++)
            s += F_s[1][i][yy] * Mw_s[(c * 5 + i) * 64 + xx];
        out[(size_t)b * 12288 + idx] = ginv * s;
    }
    __syncthreads();
    if (do_glimpse_flag)
        do_glimpse(b, x, F_s, sF_s, gamma, xce, tmp_s);
}

// ---------- host ----------
extern "C" void kernel_launch(void* const* d_in, const int* in_sizes, int n_in,
                              void* d_out, int out_size)
{
    const float* x       = (const float*)d_in[0];
    const float* y       = (const float*)d_in[1];
    const float* eps_q   = (const float*)d_in[2];
    const float* enc_Wih = (const float*)d_in[3];
    const float* enc_Whh = (const float*)d_in[4];
    const float* enc_bih = (const float*)d_in[5];
    const float* enc_bhh = (const float*)d_in[6];
    const float* dec_Wih = (const float*)d_in[7];
    const float* dec_Whh = (const float*)d_in[8];
    const float* dec_bih = (const float*)d_in[9];
    const float* dec_bhh = (const float*)d_in[10];
    const float* mu_W    = (const float*)d_in[11];
    const float* mu_b    = (const float*)d_in[12];
    const float* sig_W   = (const float*)d_in[13];
    const float* sig_b   = (const float*)d_in[14];
    const float* write_W = (const float*)d_in[15];
    const float* write_b = (const float*)d_in[16];
    const float* align_W1= (const float*)d_in[17];
    const float* align_b1= (const float*)d_in[18];
    const float* align_w2= (const float*)d_in[19];
    const float* attn_W  = (const float*)d_in[20];
    const float* attn_b  = (const float*)d_in[21];
    const float* lf_Wih  = (const float*)d_in[22];
    const float* lf_Whh  = (const float*)d_in[23];
    const float* lf_bih  = (const float*)d_in[24];
    const float* lf_bhh  = (const float*)d_in[25];
    const float* lb_Wih  = (const float*)d_in[26];
    const float* lb_Whh  = (const float*)d_in[27];
    const float* lb_bih  = (const float*)d_in[28];
    const float* lb_bhh  = (const float*)d_in[29];
    float* out = (float*)d_out;

    float* S;
    cudaGetSymbolAddress((void**)&S, S_g);

    k_init<<<4096, 256>>>(S, enc_Wih, enc_Whh, enc_bih, enc_bhh,
                          dec_Wih, dec_Whh, dec_bih, dec_bhh,
                          align_W1, lf_Whh, lb_Whh,
                          lf_bih, lf_bhh, lb_bih, lb_bhh);

    gemm2b<<<dim3(4, 64, 1), 256>>>(y, 300, lf_Wih, 300, S + OFF_BLF,
                                    S + OFF_LPRE, 512, 0u, 300, 300);
    gemm2b<<<dim3(4, 64, 1), 256>>>(y, 300, lb_Wih, 300, S + OFF_BLB,
                                    S + OFF_LPRE + 2097152u, 512, 0u, 300, 300);

    k_bilstm_pair<<<128, 512>>>(S + OFF_LPRE, S + OFF_WHT, S + OFF_HLANG);

    gemm2b<<<dim3(4, 64, 1), 256>>>(S + OFF_HLANG, 256, align_W1 + 512, 768,
                                    align_b1, S + OFF_APRE, 512, 0u, 256, 256);

    k_glimpse0<<<128, 256>>>(S + OFF_XCE, x, attn_b);

    for (int t = 0; t < 32; t++) {
        gemm2b<<<dim3(20, 2, 4), 256>>>(S + OFF_XCE, KENC, S + OFF_WENC2, KENC,
                                        nullptr, S + OFF_G, NENC, GPART, KENC, 304);

        k_enc_fused<<<128, 256>>>(S + OFF_G, S + OFF_CENC,
                                  S + OFF_XCE, S + OFF_XCD, S + OFF_BENC,
                                  mu_W, mu_b, sig_W, sig_b,
                                  eps_q + (size_t)t * 12800,
                                  S + OFF_APRE, align_w2, S + OFF_HLANG);

        gemm2b<<<dim3(16, 2, 4), 256>>>(S + OFF_XCD, KDEC, S + OFF_WDEC, KDEC,
                                        nullptr, S + OFF_G, 2048, GPART, KDEC, 224);

        k_dec_fused<<<128, 256>>>(S + OFF_G, S + OFF_CDEC,
                                  S + OFF_XCE, S + OFF_XCD, x, S + OFF_BDEC,
                                  write_W, write_b, attn_W, attn_b,
                                  out + (size_t)t * 1572864u,
                                  (t < 31) ? 1 : 0);
    }
}

// round 10
// speedup vs baseline: 3.2109x; 1.6778x over previous
#include <cuda_runtime.h>
#include <math.h>

#define KENC 1184
#define KDEC 880
#define NENC 2560
#define GPART 327680u   // 128*2560 part stride

typedef unsigned long long ull;

// ---- scratch offsets (floats) ----
#define OFF_XCE   0u
#define OFF_XCD   151552u
#define OFF_CENC  264192u
#define OFF_CDEC  329728u
#define ZEROSPAN  395264u
#define OFF_G     395264u       // 4 * 327680
#define OFF_LPRE  1705984u      // 2*4096*512
#define OFF_HLANG 5900288u      // 128*32*256
#define OFF_APRE  6948864u      // 4096*512
#define OFF_WENC2 9046016u      // 2560*1184
#define OFF_WDEC  12077056u     // 2048*880
#define OFF_BENC  13879296u     // 2560
#define OFF_BDEC  13881856u     // 2048
#define OFF_WHT   13883904u     // 2*128*512
#define OFF_BLF   14014976u     // 512
#define OFF_BLB   14015488u     // 512
#define SCR_TOTAL 14016000u

__device__ float S_g[SCR_TOTAL];

__device__ __forceinline__ float sigm(float x) { return 1.f / (1.f + expf(-x)); }
__device__ __forceinline__ ull pk2(float lo, float hi) {
    ull r; asm("mov.b64 %0,{%1,%2};" : "=l"(r) : "f"(lo), "f"(hi)); return r;
}
__device__ __forceinline__ void upk2(ull v, float& lo, float& hi) {
    asm("mov.b64 {%0,%1},%2;" : "=f"(lo), "=f"(hi) : "l"(v));
}
__device__ __forceinline__ ull fma2(ull a, ull b, ull c) {
    ull d; asm("fma.rn.f32x2 %0,%1,%2,%3;" : "=l"(d) : "l"(a), "l"(b), "l"(c)); return d;
}

// ---------- f32x2 GEMM: BM=64 BN=128 BK=16, 256 thr, double-buffered, split-K on z ----------
__global__ __launch_bounds__(256) void gemm2b(const float* __restrict__ X, int ldx,
                                              const float* __restrict__ W, int ldw,
                                              const float* __restrict__ bias,
                                              float* __restrict__ Y, int ldy,
                                              unsigned partStride, int K, int KS)
{
    __shared__ ull  As2[2][16][65];
    __shared__ float Bs[2][16][132];
    int tid = threadIdx.x;
    int m0 = blockIdx.y * 64, n0 = blockIdx.x * 128;
    int z = blockIdx.z;
    int kbeg = z * KS;
    int kend = min(K, kbeg + KS);
    float* Yp = Y + (size_t)z * partStride;
    const float* bb = (z == 0) ? bias : nullptr;
    int warp = tid >> 5, lane = tid & 31;
    int w8 = warp * 8;
    ull acc0[8], acc1[8];
#pragma unroll
    for (int i = 0; i < 8; i++) { acc0[i] = 0ull; acc1[i] = 0ull; }

    int ntile = (kend - kbeg + 15) >> 4;
    float ar[4], br[8];

    auto LDGT = [&](int k0) {
#pragma unroll
        for (int it = 0; it < 4; it++) {
            int idx = tid + it * 256;
            int m = idx >> 4, k = idx & 15;
            int gk = k0 + k;
            ar[it] = (gk < kend) ? X[(size_t)(m0 + m) * ldx + gk] : 0.f;
        }
#pragma unroll
        for (int it = 0; it < 8; it++) {
            int idx = tid + it * 256;
            int n = idx >> 4, k = idx & 15;
            int gk = k0 + k;
            br[it] = (gk < kend) ? W[(size_t)(n0 + n) * ldw + gk] : 0.f;
        }
    };
    auto STST = [&](int buf) {
#pragma unroll
        for (int it = 0; it < 4; it++) {
            int idx = tid + it * 256;
            int m = idx >> 4, k = idx & 15;
            As2[buf][k][m] = pk2(ar[it], ar[it]);
        }
#pragma unroll
        for (int it = 0; it < 8; it++) {
            int idx = tid + it * 256;
            int n = idx >> 4, k = idx & 15;
            Bs[buf][k][n] = br[it];
        }
    };

    LDGT(kbeg);
    STST(0);
    __syncthreads();
    for (int ti = 0; ti < ntile; ti++) {
        if (ti + 1 < ntile) LDGT(kbeg + (ti + 1) * 16);
        int buf = ti & 1;
#pragma unroll
        for (int kk = 0; kk < 16; kk++) {
            ull b0 = *reinterpret_cast<const ull*>(&Bs[buf][kk][2 * lane]);
            ull b1 = *reinterpret_cast<const ull*>(&Bs[buf][kk][2 * lane + 64]);
#pragma unroll
            for (int i = 0; i < 8; i++) {
                ull a = As2[buf][kk][w8 + i];
                acc0[i] = fma2(a, b0, acc0[i]);
                acc1[i] = fma2(a, b1, acc1[i]);
            }
        }
        __syncthreads();
        if (ti + 1 < ntile) {
            STST(buf ^ 1);
            __syncthreads();
        }
    }
#pragma unroll
    for (int i = 0; i < 8; i++) {
        int gm = m0 + w8 + i;
        int gn = n0 + 2 * lane;
        float lo, hi;
        upk2(acc0[i], lo, hi);
        if (bb) { lo += bb[gn]; hi += bb[gn + 1]; }
        *reinterpret_cast<float2*>(&Yp[(size_t)gm * ldy + gn]) = make_float2(lo, hi);
        upk2(acc1[i], lo, hi);
        if (bb) { lo += bb[gn + 64]; hi += bb[gn + 65]; }
        *reinterpret_cast<float2*>(&Yp[(size_t)gm * ldy + gn + 64]) = make_float2(lo, hi);
    }
}

// ---------- init ----------
#define N_WENC2 (2560u*1184u)
#define N_WDEC  (2048u*880u)
#define N_WHT   (2u*128u*512u)
#define INIT_TOTAL (ZEROSPAN + N_WENC2 + N_WDEC + 2560u + 2048u + N_WHT + 1024u)

__global__ void k_init(float* __restrict__ S,
                       const float* __restrict__ enc_Wih, const float* __restrict__ enc_Whh,
                       const float* __restrict__ enc_bih, const float* __restrict__ enc_bhh,
                       const float* __restrict__ dec_Wih, const float* __restrict__ dec_Whh,
                       const float* __restrict__ dec_bih, const float* __restrict__ dec_bhh,
                       const float* __restrict__ align_W1,
                       const float* __restrict__ lf_Whh, const float* __restrict__ lb_Whh,
                       const float* __restrict__ lf_bih, const float* __restrict__ lf_bhh,
                       const float* __restrict__ lb_bih, const float* __restrict__ lb_bhh)
{
    for (unsigned i = blockIdx.x * blockDim.x + threadIdx.x; i < INIT_TOTAL;
         i += gridDim.x * blockDim.x) {
        unsigned r = i;
        if (r < ZEROSPAN) { S[r] = 0.f; continue; }
        r -= ZEROSPAN;
        if (r < N_WENC2) {
            unsigned row = r / 1184u, col = r % 1184u;
            float v = 0.f;
            if (row < 2048u) {
                if (col < 662u) v = enc_Wih[row * 662u + col];
                else if (col < 1174u) v = enc_Whh[row * 512u + (col - 662u)];
            } else {
                if (col >= 150u && col < 662u)
                    v = align_W1[(row - 2048u) * 768u + (col - 150u)];
            }
            S[OFF_WENC2 + r] = v; continue;
        }
        r -= N_WENC2;
        if (r < N_WDEC) {
            unsigned row = r / 880u, col = r % 880u;
            float v = 0.f;
            if (col < 356u) v = dec_Wih[row * 356u + col];
            else if (col < 868u) v = dec_Whh[row * 512u + (col - 356u)];
            S[OFF_WDEC + r] = v; continue;
        }
        r -= N_WDEC;
        if (r < 2560u) {
            S[OFF_BENC + r] = (r < 2048u) ? (enc_bih[r] + enc_bhh[r]) : 0.f;
            continue;
        }
        r -= 2560u;
        if (r < 2048u) { S[OFF_BDEC + r] = dec_bih[r] + dec_bhh[r]; continue; }
        r -= 2048u;
        if (r < N_WHT) {
            unsigned dir = r / 65536u, rem = r % 65536u;
            unsigned k = rem / 512u, j = rem % 512u;
            const float* Wsrc = dir ? lb_Whh : lf_Whh;
            S[OFF_WHT + r] = Wsrc[j * 128u + k];
            continue;
        }
        r -= N_WHT;
        if (r < 512u) S[OFF_BLF + r] = lf_bih[r] + lf_bhh[r];
        else S[OFF_BLB + (r - 512u)] = lb_bih[r - 512u] + lb_bhh[r - 512u];
    }
}

// ---------- bi-LSTM: 64 blocks x 512 thr, 4 batches (2 f32x2 pairs) per block ----------
__global__ __launch_bounds__(512) void k_bilstm4(const float* __restrict__ lpre,
                                                 const float* __restrict__ WhhT,
                                                 float* __restrict__ hlang)
{
    int dir = blockIdx.x >> 5;
    int grp = blockIdx.x & 31;
    int b0 = grp * 4;
    int tid = threadIdx.x;
    __shared__ ull hA[128], hB[128];
    __shared__ float2 cA[128], cB[128];
    __shared__ ull gA[512], gB[512];
    if (tid < 128) {
        hA[tid] = 0ull; hB[tid] = 0ull;
        cA[tid] = make_float2(0.f, 0.f);
        cB[tid] = make_float2(0.f, 0.f);
    }
    __syncthreads();
    const float* Wt = WhhT + (size_t)dir * 65536;
    const float* pre = lpre + (size_t)dir * 2097152;
    int j = tid;
    for (int t = 0; t < 32; t++) {
        int tt = dir ? (31 - t) : t;
        ull aA = pk2(pre[((size_t)b0 * 32 + tt) * 512 + j],
                     pre[((size_t)(b0 + 1) * 32 + tt) * 512 + j]);
        ull aB = pk2(pre[((size_t)(b0 + 2) * 32 + tt) * 512 + j],
                     pre[((size_t)(b0 + 3) * 32 + tt) * 512 + j]);
#pragma unroll 8
        for (int k = 0; k < 128; k++) {
            float w = Wt[k * 512 + j];
            ull w2 = pk2(w, w);
            aA = fma2(w2, hA[k], aA);
            aB = fma2(w2, hB[k], aB);
        }
        gA[j] = aA;
        gB[j] = aB;
        __syncthreads();
        if (tid < 256) {
            int q = tid >> 7, u = tid & 127;
            const ull* gP = q ? gB : gA;
            float i0, i1, f0, f1, gg0, gg1, o0, o1;
            upk2(gP[u], i0, i1);
            upk2(gP[128 + u], f0, f1);
            upk2(gP[256 + u], gg0, gg1);
            upk2(gP[384 + u], o0, o1);
            float2 cc = q ? cB[u] : cA[u];
            float c20 = sigm(f0) * cc.x + sigm(i0) * tanhf(gg0);
            float c21 = sigm(f1) * cc.y + sigm(i1) * tanhf(gg1);
            float hh0 = sigm(o0) * tanhf(c20);
            float hh1 = sigm(o1) * tanhf(c21);
            if (q) { cB[u] = make_float2(c20, c21); hB[u] = pk2(hh0, hh1); }
            else   { cA[u] = make_float2(c20, c21); hA[u] = pk2(hh0, hh1); }
            int bA = b0 + 2 * q;
            hlang[((size_t)bA * 32 + tt) * 256 + dir * 128 + u] = hh0;
            hlang[((size_t)(bA + 1) * 32 + tt) * 256 + dir * 128 + u] = hh1;
        }
        __syncthreads();
    }
}

// ---------- shared filterbank (N=5), 512-thread blocks ----------
__device__ void filterbank_block(const float* p, float (*F)[5][64], float* sF, float* inv)
{
    int tid = threadIdx.x, lane = tid & 31, warp = tid >> 5;
    float gx = 32.5f * (p[0] + 1.f);
    float gy = 32.5f * (p[1] + 1.f);
    float inv2s2 = 0.5f * expf(-p[2]);
    float delta = 15.75f * expf(p[3]);
    for (int i = tid; i < 640; i += 512) {
        int f = i / 320, rem = i % 320, row = rem / 64, a = rem & 63;
        float mu = (f == 0 ? gx : gy) + ((float)row - 3.f) * delta;
        float d = (float)a - mu;
        F[f][row][a] = expf(-d * d * inv2s2);
    }
    __syncthreads();
    if (warp < 10) {
        int f = warp / 5, row = warp % 5;
        float s = F[f][row][lane] + F[f][row][lane + 32];
#pragma unroll
        for (int o = 16; o; o >>= 1) s += __shfl_xor_sync(0xffffffffu, s, o);
        if (!lane) {
            float iv = 1.f / (s + 1e-8f);
            inv[warp] = iv;
            sF[warp] = s * iv;
        }
    }
    __syncthreads();
    for (int i = tid; i < 640; i += 512) {
        int f = i / 320, rem = i % 320, row = rem / 64, a = rem & 63;
        F[f][row][a] *= inv[f * 5 + row];
    }
    __syncthreads();
}

// ---------- glimpse: x staged through padded smem (coalesced + conflict-free) ----------
__device__ void do_glimpse(int b, const float* __restrict__ x, float (*F)[5][64],
                           const float* sF, float gamma, float* __restrict__ xce,
                           float* tmp_s, float (*xs)[65])
{
    int tid = threadIdx.x, lane = tid & 31, warp = tid >> 5;
    for (int c = 0; c < 3; c++) {
        __syncthreads();
        for (int i = tid; i < 4096; i += 512)
            xs[i >> 6][i & 63] = x[(size_t)b * 12288 + c * 4096 + i];
        __syncthreads();
        if (tid < 320) {
            int yy = tid & 63, j = tid >> 6;
            float s = 0.f;
#pragma unroll 8
            for (int xx = 0; xx < 64; xx++) s += xs[yy][xx] * F[0][j][xx];
            tmp_s[(c * 5 + j) * 64 + yy] = s;
        }
    }
    __syncthreads();
    for (int o = warp; o < 75; o += 16) {
        int j = o % 5, i5 = (o / 5) % 5, c = o / 25;
        const float* tp = tmp_s + (c * 5 + j) * 64;
        float s = F[1][i5][lane] * tp[lane] + F[1][i5][lane + 32] * tp[lane + 32];
#pragma unroll
        for (int off = 16; off; off >>= 1) s += __shfl_xor_sync(0xffffffffu, s, off);
        if (!lane) {
            xce[(size_t)b * KENC + o] = s * gamma;
            xce[(size_t)b * KENC + 75 + o] = (s - 0.5f * sF[5 + i5] * sF[j]) * gamma;
        }
    }
}

// ---------- glimpse t=0 (h_dec=0 -> p=attn_b) ----------
__global__ __launch_bounds__(512) void k_glimpse0(float* __restrict__ xce,
                                                  const float* __restrict__ x,
                                                  const float* __restrict__ attn_b)
{
    int b = blockIdx.x;
    int tid = threadIdx.x;
    __shared__ float p_s[5];
    __shared__ float F_s[2][5][64];
    __shared__ float sF_s[10], inv_s[10];
    __shared__ float tmp_s[960];
    __shared__ float xs_s[64][65];
    if (tid < 5) p_s[tid] = attn_b[tid];
    __syncthreads();
    float gamma = expf(p_s[4]);
    filterbank_block(p_s, F_s, sF_s, inv_s);
    do_glimpse(b, x, F_s, sF_s, gamma, xce, tmp_s, xs_s);
}

// ---------- enc pointwise (3 parts) + mu/sig/q + align softmax + sent ----------
__global__ __launch_bounds__(512) void k_enc_fused(const float* __restrict__ G,
                                                   float* __restrict__ cenc,
                                                   float* __restrict__ xce,
                                                   float* __restrict__ xcd,
                                                   const float* __restrict__ benc,
                                                   const float* __restrict__ mu_W,
                                                   const float* __restrict__ mu_b,
                                                   const float* __restrict__ sig_W,
                                                   const float* __restrict__ sig_b,
                                                   const float* __restrict__ eps_t,
                                                   const float* __restrict__ apre,
                                                   const float* __restrict__ w2,
                                                   const float* __restrict__ hlang)
{
    int b = blockIdx.x;
    int tid = threadIdx.x, lane = tid & 31, warp = tid >> 5;
    __shared__ float h_s[512];
    __shared__ float hd_s[512];
    __shared__ float lg_s[32];
    const float* g0 = G + (size_t)b * NENC;
    {
        int u = tid;
        float gi = benc[u], gf = benc[512 + u], gg = benc[1024 + u], go = benc[1536 + u];
        float hp = 0.f;
#pragma unroll
        for (int z = 0; z < 3; z++) {
            const float* gz = g0 + (size_t)z * GPART;
            gi += gz[u]; gf += gz[512 + u]; gg += gz[1024 + u]; go += gz[1536 + u];
            hp += gz[2048 + u];
        }
        float c2 = sigm(gf) * cenc[b * 512 + u] + sigm(gi) * tanhf(gg);
        float h = sigm(go) * tanhf(c2);
        cenc[b * 512 + u] = c2;
        xce[(size_t)b * KENC + 662 + u] = h;
        h_s[u] = h;
        hd_s[u] = hp;
    }
    __syncthreads();
    for (int o = warp; o < 100; o += 16) {
        float sm = 0.f, ss = 0.f;
        const float* mr = mu_W + o * 512;
        const float* sr = sig_W + o * 512;
        for (int k = lane; k < 512; k += 32) {
            float hv = h_s[k];
            sm += mr[k] * hv;
            ss += sr[k] * hv;
        }
#pragma unroll
        for (int off = 16; off; off >>= 1) {
            sm += __shfl_xor_sync(0xffffffffu, sm, off);
            ss += __shfl_xor_sync(0xffffffffu, ss, off);
        }
        if (!lane) {
            float mu = sm + mu_b[o];
            float sg = ss + sig_b[o];
            xcd[(size_t)b * KDEC + o] = mu + eps_t[b * 100 + o] * expf(sg);
        }
    }
    for (int t = warp; t < 32; t += 16) {
        const float* ap = apre + ((size_t)b * 32 + t) * 512;
        float s = 0.f;
        for (int al = lane; al < 512; al += 32)
            s += tanhf(ap[al] + hd_s[al]) * w2[al];
#pragma unroll
        for (int o = 16; o; o >>= 1) s += __shfl_xor_sync(0xffffffffu, s, o);
        if (!lane) lg_s[t] = s;
    }
    __syncthreads();
    if (warp == 0) {
        float v = lg_s[lane];
        float m = v;
#pragma unroll
        for (int o = 16; o; o >>= 1) m = fmaxf(m, __shfl_xor_sync(0xffffffffu, m, o));
        float e = expf(v - m);
        float s = e;
#pragma unroll
        for (int o = 16; o; o >>= 1) s += __shfl_xor_sync(0xffffffffu, s, o);
        lg_s[lane] = e / s;
    }
    __syncthreads();
    if (tid < 256) {
        int jj = tid;
        float s = 0.f;
        const float* hl = hlang + (size_t)b * 8192 + jj;
#pragma unroll 8
        for (int t = 0; t < 32; t++) s += lg_s[t] * hl[t * 256];
        xcd[(size_t)b * KDEC + 100 + jj] = s;
    }
}

// ---------- dec pointwise (4 parts) + write window + OUTPUT + next-step glimpse ----------
__global__ __launch_bounds__(512) void k_dec_fused(const float* __restrict__ G,
                                                   float* __restrict__ cdec,
                                                   float* __restrict__ xce,
                                                   float* __restrict__ xcd,
                                                   const float* __restrict__ x,
                                                   const float* __restrict__ bdec,
                                                   const float* __restrict__ write_W,
                                                   const float* __restrict__ write_b,
                                                   const float* __restrict__ attn_W,
                                                   const float* __restrict__ attn_b,
                                                   float* __restrict__ out,
                                                   int do_glimpse_flag)
{
    int b = blockIdx.x;
    int tid = threadIdx.x, lane = tid & 31, warp = tid >> 5;
    __shared__ float h_s[512];
    __shared__ float w_s[75];
    __shared__ float p_s[5];
    __shared__ float F_s[2][5][64];
    __shared__ float sF_s[10], inv_s[10];
    __shared__ float Mw_s[960];
    __shared__ float tmp_s[960];
    __shared__ float xs_s[64][65];
    const float* g0 = G + (size_t)b * 2048;
    {
        int u = tid;
        float gi = bdec[u], gf = bdec[512 + u], gg = bdec[1024 + u], go = bdec[1536 + u];
#pragma unroll
        for (int z = 0; z < 4; z++) {
            const float* gz = g0 + (size_t)z * GPART;
            gi += gz[u]; gf += gz[512 + u]; gg += gz[1024 + u]; go += gz[1536 + u];
        }
        float c2 = sigm(gf) * cdec[b * 512 + u] + sigm(gi) * tanhf(gg);
        float h = sigm(go) * tanhf(c2);
        cdec[b * 512 + u] = c2;
        xce[(size_t)b * KENC + 150 + u] = h;
        xcd[(size_t)b * KDEC + 356 + u] = h;
        h_s[u] = h;
    }
    __syncthreads();
    for (int o = warp; o < 80; o += 16) {
        const float* row = (o < 75) ? (write_W + o * 512) : (attn_W + (o - 75) * 512);
        float s = 0.f;
        for (int k = lane; k < 512; k += 32) s += row[k] * h_s[k];
#pragma unroll
        for (int off = 16; off; off >>= 1) s += __shfl_xor_sync(0xffffffffu, s, off);
        if (!lane) {
            if (o < 75) w_s[o] = s + write_b[o];
            else p_s[o - 75] = s + attn_b[o - 75];
        }
    }
    __syncthreads();
    float gamma = expf(p_s[4]);
    float ginv = expf(-p_s[4]);
    filterbank_block(p_s, F_s, sF_s, inv_s);
    for (int idx = tid; idx < 960; idx += 512) {
        int xx = idx & 63, rest = idx >> 6;
        int i5 = rest % 5, c = rest / 5;
        float s = 0.f;
#pragma unroll
        for (int jj = 0; jj < 5; jj++) s += w_s[c * 25 + i5 * 5 + jj] * F_s[0][jj][xx];
        Mw_s[idx] = s;
    }
    __syncthreads();
    for (int idx = tid; idx < 12288; idx += 512) {
        int xx = idx & 63, yy = (idx >> 6) & 63, c = idx >> 12;
        float s = 0.f;
#pragma unroll
        for (int i = 0; i < 5; i++)
            s += F_s[1][i][yy] * Mw_s[(c * 5 + i) * 64 + xx];
        out[(size_t)b * 12288 + idx] = ginv * s;
    }
    if (do_glimpse_flag)
        do_glimpse(b, x, F_s, sF_s, gamma, xce, tmp_s, xs_s);
}

// ---------- host ----------
extern "C" void kernel_launch(void* const* d_in, const int* in_sizes, int n_in,
                              void* d_out, int out_size)
{
    const float* x       = (const float*)d_in[0];
    const float* y       = (const float*)d_in[1];
    const float* eps_q   = (const float*)d_in[2];
    const float* enc_Wih = (const float*)d_in[3];
    const float* enc_Whh = (const float*)d_in[4];
    const float* enc_bih = (const float*)d_in[5];
    const float* enc_bhh = (const float*)d_in[6];
    const float* dec_Wih = (const float*)d_in[7];
    const float* dec_Whh = (const float*)d_in[8];
    const float* dec_bih = (const float*)d_in[9];
    const float* dec_bhh = (const float*)d_in[10];
    const float* mu_W    = (const float*)d_in[11];
    const float* mu_b    = (const float*)d_in[12];
    const float* sig_W   = (const float*)d_in[13];
    const float* sig_b   = (const float*)d_in[14];
    const float* write_W = (const float*)d_in[15];
    const float* write_b = (const float*)d_in[16];
    const float* align_W1= (const float*)d_in[17];
    const float* align_b1= (const float*)d_in[18];
    const float* align_w2= (const float*)d_in[19];
    const float* attn_W  = (const float*)d_in[20];
    const float* attn_b  = (const float*)d_in[21];
    const float* lf_Wih  = (const float*)d_in[22];
    const float* lf_Whh  = (const float*)d_in[23];
    const float* lf_bih  = (const float*)d_in[24];
    const float* lf_bhh  = (const float*)d_in[25];
    const float* lb_Wih  = (const float*)d_in[26];
    const float* lb_Whh  = (const float*)d_in[27];
    const float* lb_bih  = (const float*)d_in[28];
    const float* lb_bhh  = (const float*)d_in[29];
    float* out = (float*)d_out;

    float* S;
    cudaGetSymbolAddress((void**)&S, S_g);

    k_init<<<4096, 256>>>(S, enc_Wih, enc_Whh, enc_bih, enc_bhh,
                          dec_Wih, dec_Whh, dec_bih, dec_bhh,
                          align_W1, lf_Whh, lb_Whh,
                          lf_bih, lf_bhh, lb_bih, lb_bhh);

    gemm2b<<<dim3(4, 64, 1), 256>>>(y, 300, lf_Wih, 300, S + OFF_BLF,
                                    S + OFF_LPRE, 512, 0u, 300, 300);
    gemm2b<<<dim3(4, 64, 1), 256>>>(y, 300, lb_Wih, 300, S + OFF_BLB,
                                    S + OFF_LPRE + 2097152u, 512, 0u, 300, 300);

    k_bilstm4<<<64, 512>>>(S + OFF_LPRE, S + OFF_WHT, S + OFF_HLANG);

    gemm2b<<<dim3(4, 64, 1), 256>>>(S + OFF_HLANG, 256, align_W1 + 512, 768,
                                    align_b1, S + OFF_APRE, 512, 0u, 256, 256);

    k_glimpse0<<<128, 512>>>(S + OFF_XCE, x, attn_b);

    for (int t = 0; t < 32; t++) {
        // enc gates + hdproj: M=128 N=2560 K=1184, split-K=3 (400/400/384) -> 120 blocks
        gemm2b<<<dim3(20, 2, 3), 256>>>(S + OFF_XCE, KENC, S + OFF_WENC2, KENC,
                                        nullptr, S + OFF_G, NENC, GPART, KENC, 400);

        k_enc_fused<<<128, 512>>>(S + OFF_G, S + OFF_CENC,
                                  S + OFF_XCE, S + OFF_XCD, S + OFF_BENC,
                                  mu_W, mu_b, sig_W, sig_b,
                                  eps_q + (size_t)t * 12800,
                                  S + OFF_APRE, align_w2, S + OFF_HLANG);

        // dec gates: M=128 N=2048 K=880, split-K=4 (224) -> 128 blocks
        gemm2b<<<dim3(16, 2, 4), 256>>>(S + OFF_XCD, KDEC, S + OFF_WDEC, KDEC,
                                        nullptr, S + OFF_G, 2048, GPART, KDEC, 224);

        k_dec_fused<<<128, 512>>>(S + OFF_G, S + OFF_CDEC,
                                  S + OFF_XCE, S + OFF_XCD, x, S + OFF_BDEC,
                                  write_W, write_b, attn_W, attn_b,
                                  out + (size_t)t * 1572864u,
                                  (t < 31) ? 1 : 0);
    }
}

// round 11
// speedup vs baseline: 3.2557x; 1.0139x over previous
#include <cuda_runtime.h>
#include <math.h>

#define KENC 1184
#define KDEC 880
#define NENC 2560
#define GPART 327680u   // 128*2560 part stride
#define NB 128          // megakernel blocks

typedef unsigned long long ull;

// ---- scratch offsets (floats) ----
#define OFF_XCE   0u
#define OFF_XCD   151552u
#define OFF_CENC  264192u
#define OFF_CDEC  329728u
#define ZEROSPAN  395264u
#define OFF_G     395264u       // 4 * 327680
#define OFF_LPRE  1705984u      // 2*4096*512
#define OFF_HLANG 5900288u      // 128*32*256
#define OFF_APRE  6948864u      // 4096*512
#define OFF_WENC2 9046016u      // 2560*1184
#define OFF_WDEC  12077056u     // 2048*880
#define OFF_BENC  13879296u     // 2560
#define OFF_BDEC  13881856u     // 2048
#define OFF_WHT   13883904u     // 2*128*512
#define OFF_BLF   14014976u     // 512
#define OFF_BLB   14015488u     // 512
#define SCR_TOTAL 14016000u

__device__ float S_g[SCR_TOTAL];
__device__ unsigned g_cnt;
__device__ unsigned g_gen;

__device__ __forceinline__ float sigm(float x) { return 1.f / (1.f + expf(-x)); }
__device__ __forceinline__ ull pk2(float lo, float hi) {
    ull r; asm("mov.b64 %0,{%1,%2};" : "=l"(r) : "f"(lo), "f"(hi)); return r;
}
__device__ __forceinline__ void upk2(ull v, float& lo, float& hi) {
    asm("mov.b64 {%0,%1},%2;" : "=f"(lo), "=f"(hi) : "l"(v));
}
__device__ __forceinline__ ull fma2(ull a, ull b, ull c) {
    ull d; asm("fma.rn.f32x2 %0,%1,%2,%3;" : "=l"(d) : "l"(a), "l"(b), "l"(c)); return d;
}

// ---------- grid barrier (cooperative-groups style; gpu fence -> CCTL.IVALL) ----------
__device__ __forceinline__ void gsync() {
    __syncthreads();
    if (threadIdx.x == 0) {
        __threadfence();
        unsigned gen = *((volatile unsigned*)&g_gen);
        if (atomicAdd(&g_cnt, 1u) == NB - 1u) {
            atomicExch(&g_cnt, 0u);
            __threadfence();
            atomicExch(&g_gen, gen + 1u);
        } else {
            while (*((volatile unsigned*)&g_gen) == gen) {}
        }
        __threadfence();
    }
    __syncthreads();
}

// ---------- shared memory overlays ----------
struct SmemGemm {
    ull  As2[2][16][65];
    float Bs[2][16][132];
};
struct SmemFused {
    float h_s[512];
    float hd_s[512];
    float lg_s[32];
    float w_s[80];
    float p_s[5];
    float F_s[2][5][64];
    float sF_s[10], inv_s[10];
    float Mw_s[960];
    float tmp_s[960];
    float xs_s[64][65];
};

// ---------- standalone f32x2 GEMM (prologue; 256 thr, double-buffered) ----------
__global__ __launch_bounds__(256) void gemm2b(const float* __restrict__ X, int ldx,
                                              const float* __restrict__ W, int ldw,
                                              const float* __restrict__ bias,
                                              float* __restrict__ Y, int ldy, int K)
{
    __shared__ ull  As2[2][16][65];
    __shared__ float Bs[2][16][132];
    int tid = threadIdx.x;
    int m0 = blockIdx.y * 64, n0 = blockIdx.x * 128;
    int warp = tid >> 5, lane = tid & 31;
    int w8 = warp * 8;
    ull acc0[8], acc1[8];
#pragma unroll
    for (int i = 0; i < 8; i++) { acc0[i] = 0ull; acc1[i] = 0ull; }
    int ntile = (K + 15) >> 4;
    float ar[4], br[8];
    auto LDGT = [&](int k0) {
#pragma unroll
        for (int it = 0; it < 4; it++) {
            int idx = tid + it * 256;
            int m = idx >> 4, k = idx & 15;
            int gk = k0 + k;
            ar[it] = (gk < K) ? X[(size_t)(m0 + m) * ldx + gk] : 0.f;
        }
#pragma unroll
        for (int it = 0; it < 8; it++) {
            int idx = tid + it * 256;
            int n = idx >> 4, k = idx & 15;
            int gk = k0 + k;
            br[it] = (gk < K) ? W[(size_t)(n0 + n) * ldw + gk] : 0.f;
        }
    };
    auto STST = [&](int buf) {
#pragma unroll
        for (int it = 0; it < 4; it++) {
            int idx = tid + it * 256;
            As2[buf][idx & 15][idx >> 4] = pk2(ar[it], ar[it]);
        }
#pragma unroll
        for (int it = 0; it < 8; it++) {
            int idx = tid + it * 256;
            Bs[buf][idx & 15][idx >> 4] = br[it];
        }
    };
    LDGT(0); STST(0); __syncthreads();
    for (int ti = 0; ti < ntile; ti++) {
        if (ti + 1 < ntile) LDGT((ti + 1) * 16);
        int buf = ti & 1;
#pragma unroll
        for (int kk = 0; kk < 16; kk++) {
            ull b0 = *reinterpret_cast<const ull*>(&Bs[buf][kk][2 * lane]);
            ull b1 = *reinterpret_cast<const ull*>(&Bs[buf][kk][2 * lane + 64]);
#pragma unroll
            for (int i = 0; i < 8; i++) {
                ull a = As2[buf][kk][w8 + i];
                acc0[i] = fma2(a, b0, acc0[i]);
                acc1[i] = fma2(a, b1, acc1[i]);
            }
        }
        __syncthreads();
        if (ti + 1 < ntile) { STST(buf ^ 1); __syncthreads(); }
    }
#pragma unroll
    for (int i = 0; i < 8; i++) {
        int gm = m0 + w8 + i;
        int gn = n0 + 2 * lane;
        float lo, hi;
        upk2(acc0[i], lo, hi);
        lo += bias[gn]; hi += bias[gn + 1];
        *reinterpret_cast<float2*>(&Y[(size_t)gm * ldy + gn]) = make_float2(lo, hi);
        upk2(acc1[i], lo, hi);
        lo += bias[gn + 64]; hi += bias[gn + 65];
        *reinterpret_cast<float2*>(&Y[(size_t)gm * ldy + gn + 64]) = make_float2(lo, hi);
    }
}

// ---------- init ----------
#define N_WENC2 (2560u*1184u)
#define N_WDEC  (2048u*880u)
#define N_WHT   (2u*128u*512u)
#define INIT_TOTAL (ZEROSPAN + N_WENC2 + N_WDEC + 2560u + 2048u + N_WHT + 1024u)

__global__ void k_init(float* __restrict__ S,
                       const float* __restrict__ enc_Wih, const float* __restrict__ enc_Whh,
                       const float* __restrict__ enc_bih, const float* __restrict__ enc_bhh,
                       const float* __restrict__ dec_Wih, const float* __restrict__ dec_Whh,
                       const float* __restrict__ dec_bih, const float* __restrict__ dec_bhh,
                       const float* __restrict__ align_W1,
                       const float* __restrict__ lf_Whh, const float* __restrict__ lb_Whh,
                       const float* __restrict__ lf_bih, const float* __restrict__ lf_bhh,
                       const float* __restrict__ lb_bih, const float* __restrict__ lb_bhh)
{
    for (unsigned i = blockIdx.x * blockDim.x + threadIdx.x; i < INIT_TOTAL;
         i += gridDim.x * blockDim.x) {
        unsigned r = i;
        if (r < ZEROSPAN) { S[r] = 0.f; continue; }
        r -= ZEROSPAN;
        if (r < N_WENC2) {
            unsigned row = r / 1184u, col = r % 1184u;
            float v = 0.f;
            if (row < 2048u) {
                if (col < 662u) v = enc_Wih[row * 662u + col];
                else if (col < 1174u) v = enc_Whh[row * 512u + (col - 662u)];
            } else {
                if (col >= 150u && col < 662u)
                    v = align_W1[(row - 2048u) * 768u + (col - 150u)];
            }
            S[OFF_WENC2 + r] = v; continue;
        }
        r -= N_WENC2;
        if (r < N_WDEC) {
            unsigned row = r / 880u, col = r % 880u;
            float v = 0.f;
            if (col < 356u) v = dec_Wih[row * 356u + col];
            else if (col < 868u) v = dec_Whh[row * 512u + (col - 356u)];
            S[OFF_WDEC + r] = v; continue;
        }
        r -= N_WDEC;
        if (r < 2560u) {
            S[OFF_BENC + r] = (r < 2048u) ? (enc_bih[r] + enc_bhh[r]) : 0.f;
            continue;
        }
        r -= 2560u;
        if (r < 2048u) { S[OFF_BDEC + r] = dec_bih[r] + dec_bhh[r]; continue; }
        r -= 2048u;
        if (r < N_WHT) {
            unsigned dir = r / 65536u, rem = r % 65536u;
            unsigned k = rem / 512u, j = rem % 512u;
            const float* Wsrc = dir ? lb_Whh : lf_Whh;
            S[OFF_WHT + r] = Wsrc[j * 128u + k];
            continue;
        }
        r -= N_WHT;
        if (r < 512u) S[OFF_BLF + r] = lf_bih[r] + lf_bhh[r];
        else S[OFF_BLB + (r - 512u)] = lb_bih[r - 512u] + lb_bhh[r - 512u];
    }
}

// ---------- bi-LSTM: 128 blocks x 512 thr, one f32x2 batch-pair per block ----------
__global__ __launch_bounds__(512) void k_bilstm_pair(const float* __restrict__ lpre,
                                                     const float* __restrict__ WhhT,
                                                     float* __restrict__ hlang)
{
    int dir = blockIdx.x >> 6;
    int pr = blockIdx.x & 63;
    int b0 = pr * 2;
    int tid = threadIdx.x;
    __shared__ ull h2[128];
    __shared__ float2 c2s[128];
    __shared__ ull g2[512];
    if (tid < 128) { h2[tid] = 0ull; c2s[tid] = make_float2(0.f, 0.f); }
    __syncthreads();
    const float* Wt = WhhT + (size_t)dir * 65536;
    const float* pre = lpre + (size_t)dir * 2097152;
    int j = tid;
    for (int t = 0; t < 32; t++) {
        int tt = dir ? (31 - t) : t;
        float lo = pre[((size_t)b0 * 32 + tt) * 512 + j];
        float hi = pre[((size_t)(b0 + 1) * 32 + tt) * 512 + j];
        ull acc = pk2(lo, hi);
#pragma unroll 8
        for (int k = 0; k < 128; k++) {
            float w = Wt[k * 512 + j];
            acc = fma2(pk2(w, w), h2[k], acc);
        }
        g2[j] = acc;
        __syncthreads();
        if (tid < 128) {
            int u = tid;
            float i0, i1, f0, f1, gg0, gg1, o0, o1;
            upk2(g2[u], i0, i1);
            upk2(g2[128 + u], f0, f1);
            upk2(g2[256 + u], gg0, gg1);
            upk2(g2[384 + u], o0, o1);
            float2 cc = c2s[u];
            float c20 = sigm(f0) * cc.x + sigm(i0) * tanhf(gg0);
            float c21 = sigm(f1) * cc.y + sigm(i1) * tanhf(gg1);
            float hh0 = sigm(o0) * tanhf(c20);
            float hh1 = sigm(o1) * tanhf(c21);
            c2s[u] = make_float2(c20, c21);
            h2[u] = pk2(hh0, hh1);
            hlang[((size_t)b0 * 32 + tt) * 256 + dir * 128 + u] = hh0;
            hlang[((size_t)(b0 + 1) * 32 + tt) * 256 + dir * 128 + u] = hh1;
        }
        __syncthreads();
    }
}

// ---------- shared filterbank (N=5), 512 threads ----------
__device__ void filterbank_block(const float* p, float (*F)[5][64], float* sF, float* inv)
{
    int tid = threadIdx.x, lane = tid & 31, warp = tid >> 5;
    float gx = 32.5f * (p[0] + 1.f);
    float gy = 32.5f * (p[1] + 1.f);
    float inv2s2 = 0.5f * expf(-p[2]);
    float delta = 15.75f * expf(p[3]);
    for (int i = tid; i < 640; i += 512) {
        int f = i / 320, rem = i % 320, row = rem / 64, a = rem & 63;
        float mu = (f == 0 ? gx : gy) + ((float)row - 3.f) * delta;
        float d = (float)a - mu;
        F[f][row][a] = expf(-d * d * inv2s2);
    }
    __syncthreads();
    if (warp < 10) {
        int f = warp / 5, row = warp % 5;
        float s = F[f][row][lane] + F[f][row][lane + 32];
#pragma unroll
        for (int o = 16; o; o >>= 1) s += __shfl_xor_sync(0xffffffffu, s, o);
        if (!lane) {
            float iv = 1.f / (s + 1e-8f);
            inv[warp] = iv;
            sF[warp] = s * iv;
        }
    }
    __syncthreads();
    for (int i = tid; i < 640; i += 512) {
        int f = i / 320, rem = i % 320, row = rem / 64, a = rem & 63;
        F[f][row][a] *= inv[f * 5 + row];
    }
    __syncthreads();
}

// ---------- glimpse (x staged through padded smem) ----------
__device__ void do_glimpse(int b, const float* __restrict__ x, float (*F)[5][64],
                           const float* sF, float gamma, float* __restrict__ xce,
                           float* tmp_s, float (*xs)[65])
{
    int tid = threadIdx.x, lane = tid & 31, warp = tid >> 5;
    for (int c = 0; c < 3; c++) {
        __syncthreads();
        for (int i = tid; i < 4096; i += 512)
            xs[i >> 6][i & 63] = x[(size_t)b * 12288 + c * 4096 + i];
        __syncthreads();
        if (tid < 320) {
            int yy = tid & 63, j = tid >> 6;
            float s = 0.f;
#pragma unroll 8
            for (int xx = 0; xx < 64; xx++) s += xs[yy][xx] * F[0][j][xx];
            tmp_s[(c * 5 + j) * 64 + yy] = s;
        }
    }
    __syncthreads();
    for (int o = warp; o < 75; o += 16) {
        int j = o % 5, i5 = (o / 5) % 5, c = o / 25;
        const float* tp = tmp_s + (c * 5 + j) * 64;
        float s = F[1][i5][lane] * tp[lane] + F[1][i5][lane + 32] * tp[lane + 32];
#pragma unroll
        for (int off = 16; off; off >>= 1) s += __shfl_xor_sync(0xffffffffu, s, off);
        if (!lane) {
            xce[(size_t)b * KENC + o] = s * gamma;
            xce[(size_t)b * KENC + 75 + o] = (s - 0.5f * sF[5 + i5] * sF[j]) * gamma;
        }
    }
}

// ---------- glimpse t=0 ----------
__global__ __launch_bounds__(512) void k_glimpse0(float* __restrict__ xce,
                                                  const float* __restrict__ x,
                                                  const float* __restrict__ attn_b)
{
    int b = blockIdx.x;
    int tid = threadIdx.x;
    __shared__ float p_s[5];
    __shared__ float F_s[2][5][64];
    __shared__ float sF_s[10], inv_s[10];
    __shared__ float tmp_s[960];
    __shared__ float xs_s[64][65];
    if (tid < 5) p_s[tid] = attn_b[tid];
    __syncthreads();
    float gamma = expf(p_s[4]);
    filterbank_block(p_s, F_s, sF_s, inv_s);
    do_glimpse(b, x, F_s, sF_s, gamma, xce, tmp_s, xs_s);
}

// ---------- in-megakernel GEMM phase (512 threads, 64x128x16, double-buffered) ----------
__device__ void gemm_phase512(SmemGemm& sm,
                              const float* __restrict__ X, int ldx,
                              const float* __restrict__ W, int ldw,
                              float* __restrict__ Yp, int ldy,
                              int m0, int n0, int kbeg, int kend)
{
    int tid = threadIdx.x;
    int warp = tid >> 5, lane = tid & 31;
    int w4 = warp * 4;
    ull acc0[4] = {0ull, 0ull, 0ull, 0ull};
    ull acc1[4] = {0ull, 0ull, 0ull, 0ull};
    int ntile = (kend - kbeg + 15) >> 4;
    float ar[2], br[4];
    auto LDGT = [&](int k0) {
#pragma unroll
        for (int it = 0; it < 2; it++) {
            int idx = tid + it * 512;
            int m = idx >> 4, k = idx & 15;
            int gk = k0 + k;
            ar[it] = (gk < kend) ? X[(size_t)(m0 + m) * ldx + gk] : 0.f;
        }
#pragma unroll
        for (int it = 0; it < 4; it++) {
            int idx = tid + it * 512;
            int n = idx >> 4, k = idx & 15;
            int gk = k0 + k;
            br[it] = (gk < kend) ? W[(size_t)(n0 + n) * ldw + gk] : 0.f;
        }
    };
    auto STST = [&](int buf) {
#pragma unroll
        for (int it = 0; it < 2; it++) {
            int idx = tid + it * 512;
            sm.As2[buf][idx & 15][idx >> 4] = pk2(ar[it], ar[it]);
        }
#pragma unroll
        for (int it = 0; it < 4; it++) {
            int idx = tid + it * 512;
            sm.Bs[buf][idx & 15][idx >> 4] = br[it];
        }
    };
    LDGT(kbeg); STST(0); __syncthreads();
    for (int ti = 0; ti < ntile; ti++) {
        if (ti + 1 < ntile) LDGT(kbeg + (ti + 1) * 16);
        int buf = ti & 1;
#pragma unroll
        for (int kk = 0; kk < 16; kk++) {
            ull b0 = *reinterpret_cast<const ull*>(&sm.Bs[buf][kk][2 * lane]);
            ull b1 = *reinterpret_cast<const ull*>(&sm.Bs[buf][kk][2 * lane + 64]);
#pragma unroll
            for (int i = 0; i < 4; i++) {
                ull a = sm.As2[buf][kk][w4 + i];
                acc0[i] = fma2(a, b0, acc0[i]);
                acc1[i] = fma2(a, b1, acc1[i]);
            }
        }
        __syncthreads();
        if (ti + 1 < ntile) { STST(buf ^ 1); __syncthreads(); }
    }
#pragma unroll
    for (int i = 0; i < 4; i++) {
        int gm = m0 + w4 + i;
        int gn = n0 + 2 * lane;
        float lo, hi;
        upk2(acc0[i], lo, hi);
        *reinterpret_cast<float2*>(&Yp[(size_t)gm * ldy + gn]) = make_float2(lo, hi);
        upk2(acc1[i], lo, hi);
        *reinterpret_cast<float2*>(&Yp[(size_t)gm * ldy + gn + 64]) = make_float2(lo, hi);
    }
}

// ---------- enc fused phase ----------
__device__ void enc_phase(SmemFused& sf, int b, const float* __restrict__ G,
                          float* __restrict__ cenc, float* __restrict__ xce,
                          float* __restrict__ xcd, const float* __restrict__ benc,
                          const float* __restrict__ mu_W, const float* __restrict__ mu_b,
                          const float* __restrict__ sig_W, const float* __restrict__ sig_b,
                          const float* __restrict__ eps_t, const float* __restrict__ apre,
                          const float* __restrict__ w2, const float* __restrict__ hlang)
{
    int tid = threadIdx.x, lane = tid & 31, warp = tid >> 5;
    const float* g0 = G + (size_t)b * NENC;
    {
        int u = tid;
        float gi = benc[u], gf = benc[512 + u], gg = benc[1024 + u], go = benc[1536 + u];
        float hp = 0.f;
#pragma unroll
        for (int z = 0; z < 3; z++) {
            const float* gz = g0 + (size_t)z * GPART;
            gi += gz[u]; gf += gz[512 + u]; gg += gz[1024 + u]; go += gz[1536 + u];
            hp += gz[2048 + u];
        }
        float c2 = sigm(gf) * cenc[b * 512 + u] + sigm(gi) * tanhf(gg);
        float h = sigm(go) * tanhf(c2);
        cenc[b * 512 + u] = c2;
        xce[(size_t)b * KENC + 662 + u] = h;
        sf.h_s[u] = h;
        sf.hd_s[u] = hp;
    }
    __syncthreads();
    for (int o = warp; o < 100; o += 16) {
        float sm = 0.f, ss = 0.f;
        const float* mr = mu_W + o * 512;
        const float* sr = sig_W + o * 512;
        for (int k = lane; k < 512; k += 32) {
            float hv = sf.h_s[k];
            sm += mr[k] * hv;
            ss += sr[k] * hv;
        }
#pragma unroll
        for (int off = 16; off; off >>= 1) {
            sm += __shfl_xor_sync(0xffffffffu, sm, off);
            ss += __shfl_xor_sync(0xffffffffu, ss, off);
        }
        if (!lane) {
            float mu = sm + mu_b[o];
            float sg = ss + sig_b[o];
            xcd[(size_t)b * KDEC + o] = mu + eps_t[b * 100 + o] * expf(sg);
        }
    }
    for (int t = warp; t < 32; t += 16) {
        const float* ap = apre + ((size_t)b * 32 + t) * 512;
        float s = 0.f;
        for (int al = lane; al < 512; al += 32)
            s += tanhf(ap[al] + sf.hd_s[al]) * w2[al];
#pragma unroll
        for (int o = 16; o; o >>= 1) s += __shfl_xor_sync(0xffffffffu, s, o);
        if (!lane) sf.lg_s[t] = s;
    }
    __syncthreads();
    if (warp == 0) {
        float v = sf.lg_s[lane];
        float m = v;
#pragma unroll
        for (int o = 16; o; o >>= 1) m = fmaxf(m, __shfl_xor_sync(0xffffffffu, m, o));
        float e = expf(v - m);
        float s = e;
#pragma unroll
        for (int o = 16; o; o >>= 1) s += __shfl_xor_sync(0xffffffffu, s, o);
        sf.lg_s[lane] = e / s;
    }
    __syncthreads();
    if (tid < 256) {
        int jj = tid;
        float s = 0.f;
        const float* hl = hlang + (size_t)b * 8192 + jj;
#pragma unroll 8
        for (int t = 0; t < 32; t++) s += sf.lg_s[t] * hl[t * 256];
        xcd[(size_t)b * KDEC + 100 + jj] = s;
    }
}

// ---------- dec fused phase (+ output + next glimpse) ----------
__device__ void dec_phase(SmemFused& sf, int b, const float* __restrict__ G,
                          float* __restrict__ cdec, float* __restrict__ xce,
                          float* __restrict__ xcd, const float* __restrict__ x,
                          const float* __restrict__ bdec,
                          const float* __restrict__ write_W, const float* __restrict__ write_b,
                          const float* __restrict__ attn_W, const float* __restrict__ attn_b,
                          float* __restrict__ out_t, int doGlimpse)
{
    int tid = threadIdx.x, lane = tid & 31, warp = tid >> 5;
    const float* g0 = G + (size_t)b * 2048;
    {
        int u = tid;
        float gi = bdec[u], gf = bdec[512 + u], gg = bdec[1024 + u], go = bdec[1536 + u];
#pragma unroll
        for (int z = 0; z < 4; z++) {
            const float* gz = g0 + (size_t)z * GPART;
            gi += gz[u]; gf += gz[512 + u]; gg += gz[1024 + u]; go += gz[1536 + u];
        }
        float c2 = sigm(gf) * cdec[b * 512 + u] + sigm(gi) * tanhf(gg);
        float h = sigm(go) * tanhf(c2);
        cdec[b * 512 + u] = c2;
        xce[(size_t)b * KENC + 150 + u] = h;
        xcd[(size_t)b * KDEC + 356 + u] = h;
        sf.h_s[u] = h;
    }
    __syncthreads();
    for (int o = warp; o < 80; o += 16) {
        const float* row = (o < 75) ? (write_W + o * 512) : (attn_W + (o - 75) * 512);
        float s = 0.f;
        for (int k = lane; k < 512; k += 32) s += row[k] * sf.h_s[k];
#pragma unroll
        for (int off = 16; off; off >>= 1) s += __shfl_xor_sync(0xffffffffu, s, off);
        if (!lane) {
            if (o < 75) sf.w_s[o] = s + write_b[o];
            else sf.p_s[o - 75] = s + attn_b[o - 75];
        }
    }
    __syncthreads();
    float gamma = expf(sf.p_s[4]);
    float ginv = expf(-sf.p_s[4]);
    filterbank_block(sf.p_s, sf.F_s, sf.sF_s, sf.inv_s);
    for (int idx = tid; idx < 960; idx += 512) {
        int xx = idx & 63, rest = idx >> 6;
        int i5 = rest % 5, c = rest / 5;
        float s = 0.f;
#pragma unroll
        for (int jj = 0; jj < 5; jj++) s += sf.w_s[c * 25 + i5 * 5 + jj] * sf.F_s[0][jj][xx];
        sf.Mw_s[idx] = s;
    }
    __syncthreads();
    for (int idx = tid; idx < 12288; idx += 512) {
        int xx = idx & 63, yy = (idx >> 6) & 63, c = idx >> 12;
        float s = 0.f;
#pragma unroll
        for (int i = 0; i < 5; i++)
            s += sf.F_s[1][i][yy] * sf.Mw_s[(c * 5 + i) * 64 + xx];
        out_t[(size_t)b * 12288 + idx] = ginv * s;
    }
    if (doGlimpse)
        do_glimpse(b, x, sf.F_s, sf.sF_s, gamma, xce, sf.tmp_s, sf.xs_s);
}

// ---------- persistent scan megakernel: 128 blocks x 512 thr ----------
__global__ __launch_bounds__(512) void k_scan(float* __restrict__ S,
                                              const float* __restrict__ x,
                                              const float* __restrict__ eps_q,
                                              const float* __restrict__ mu_W,
                                              const float* __restrict__ mu_b,
                                              const float* __restrict__ sig_W,
                                              const float* __restrict__ sig_b,
                                              const float* __restrict__ write_W,
                                              const float* __restrict__ write_b,
                                              const float* __restrict__ attn_W,
                                              const float* __restrict__ attn_b,
                                              const float* __restrict__ w2,
                                              float* __restrict__ out)
{
    __shared__ __align__(16) char smraw[sizeof(SmemGemm)];
    SmemGemm& sg = *reinterpret_cast<SmemGemm*>(smraw);
    SmemFused& sf = *reinterpret_cast<SmemFused*>(smraw);
    int blk = blockIdx.x;
    float* xce = S + OFF_XCE;
    float* xcd = S + OFF_XCD;
    float* G   = S + OFF_G;

    for (int t = 0; t < 32; t++) {
        // --- ENC GEMM: M=128 N=2560 K=1184, split-K=3 (400/400/384), 120 units ---
        if (blk < 120) {
            int z = blk / 40, rem = blk % 40;
            int my = rem / 20, nx = rem % 20;
            int kbeg = z * 400, kend = min(KENC, kbeg + 400);
            gemm_phase512(sg, xce, KENC, S + OFF_WENC2, KENC,
                          G + (size_t)z * GPART, NENC,
                          my * 64, nx * 128, kbeg, kend);
        }
        gsync();
        // --- ENC FUSED ---
        enc_phase(sf, blk, G, S + OFF_CENC, xce, xcd, S + OFF_BENC,
                  mu_W, mu_b, sig_W, sig_b,
                  eps_q + (size_t)t * 12800, S + OFF_APRE, w2, S + OFF_HLANG);
        gsync();
        // --- DEC GEMM: M=128 N=2048 K=880, split-K=4 (224), 128 units ---
        {
            int z = blk >> 5, rem = blk & 31;
            int my = rem >> 4, nx = rem & 15;
            int kbeg = z * 224, kend = min(KDEC, kbeg + 224);
            gemm_phase512(sg, xcd, KDEC, S + OFF_WDEC, KDEC,
                          G + (size_t)z * GPART, 2048,
                          my * 64, nx * 128, kbeg, kend);
        }
        gsync();
        // --- DEC FUSED + output + next glimpse ---
        dec_phase(sf, blk, G, S + OFF_CDEC, xce, xcd, x, S + OFF_BDEC,
                  write_W, write_b, attn_W, attn_b,
                  out + (size_t)t * 1572864u, (t < 31) ? 1 : 0);
        if (t < 31) gsync();
    }
}

// ---------- host ----------
extern "C" void kernel_launch(void* const* d_in, const int* in_sizes, int n_in,
                              void* d_out, int out_size)
{
    const float* x       = (const float*)d_in[0];
    const float* y       = (const float*)d_in[1];
    const float* eps_q   = (const float*)d_in[2];
    const float* enc_Wih = (const float*)d_in[3];
    const float* enc_Whh = (const float*)d_in[4];
    const float* enc_bih = (const float*)d_in[5];
    const float* enc_bhh = (const float*)d_in[6];
    const float* dec_Wih = (const float*)d_in[7];
    const float* dec_Whh = (const float*)d_in[8];
    const float* dec_bih = (const float*)d_in[9];
    const float* dec_bhh = (const float*)d_in[10];
    const float* mu_W    = (const float*)d_in[11];
    const float* mu_b    = (const float*)d_in[12];
    const float* sig_W   = (const float*)d_in[13];
    const float* sig_b   = (const float*)d_in[14];
    const float* write_W = (const float*)d_in[15];
    const float* write_b = (const float*)d_in[16];
    const float* align_W1= (const float*)d_in[17];
    const float* align_b1= (const float*)d_in[18];
    const float* align_w2= (const float*)d_in[19];
    const float* attn_W  = (const float*)d_in[20];
    const float* attn_b  = (const float*)d_in[21];
    const float* lf_Wih  = (const float*)d_in[22];
    const float* lf_Whh  = (const float*)d_in[23];
    const float* lf_bih  = (const float*)d_in[24];
    const float* lf_bhh  = (const float*)d_in[25];
    const float* lb_Wih  = (const float*)d_in[26];
    const float* lb_Whh  = (const float*)d_in[27];
    const float* lb_bih  = (const float*)d_in[28];
    const float* lb_bhh  = (const float*)d_in[29];
    float* out = (float*)d_out;

    float* S;
    cudaGetSymbolAddress((void**)&S, S_g);

    k_init<<<4096, 256>>>(S, enc_Wih, enc_Whh, enc_bih, enc_bhh,
                          dec_Wih, dec_Whh, dec_bih, dec_bhh,
                          align_W1, lf_Whh, lb_Whh,
                          lf_bih, lf_bhh, lb_bih, lb_bhh);

    gemm2b<<<dim3(4, 64), 256>>>(y, 300, lf_Wih, 300, S + OFF_BLF,
                                 S + OFF_LPRE, 512, 300);
    gemm2b<<<dim3(4, 64), 256>>>(y, 300, lb_Wih, 300, S + OFF_BLB,
                                 S + OFF_LPRE + 2097152u, 512, 300);

    k_bilstm_pair<<<128, 512>>>(S + OFF_LPRE, S + OFF_WHT, S + OFF_HLANG);

    gemm2b<<<dim3(4, 64), 256>>>(S + OFF_HLANG, 256, align_W1 + 512, 768,
                                 align_b1, S + OFF_APRE, 512, 256);

    k_glimpse0<<<128, 512>>>(S + OFF_XCE, x, attn_b);

    k_scan<<<NB, 512>>>(S, x, eps_q, mu_W, mu_b, sig_W, sig_b,
                        write_W, write_b, attn_W, attn_b, align_w2, out);
}